// round 4
// baseline (speedup 1.0000x reference)
#include <cuda_runtime.h>
#include <math.h>

#define DD 64
#define LL 64
#define DIMF 512
#define GG 256
#define MNODES 192
#define KNN 12
#define NROWS 4096
#define TAUF 0.07f

// ---------------- device scratch (no allocations allowed) ----------------
__device__ float g_X[DD*MNODES*GG];              // fc output      [d,m,G]
__device__ float g_E[DD*MNODES*GG];              // edge features  [d,m,G]
__device__ float g_Y[DD*MNODES*GG];              // node features  [d,m,G]
__device__ unsigned long long g_H[DD*MNODES*3];  // incidence bitmask rows
__device__ float g_xn[3*NROWS*GG];               // normalized tn/an/vn
__device__ float g_lse[6*NROWS];                 // per-row logsumexp (6 ordered pairs)
__device__ float g_diag[3*NROWS];                // per-row diag sim (3 pairs)

__device__ __forceinline__ const float* feat_row(const float* t, const float* a,
                                                 const float* v, int d, int n) {
    int mod = n >> 6;            // 0:t 1:a 2:v
    int i   = n & 63;
    const float* b = (mod == 0) ? t : (mod == 1) ? a : v;
    return b + (size_t)(d * LL + i) * DIMF;
}

// ---------------- X = feat @ W_fc + b_fc  (M=12288,K=512,N=256) ----------------
__global__ void fc_gemm_kernel(const float* __restrict__ t, const float* __restrict__ a,
                               const float* __restrict__ v, const float* __restrict__ Wfc,
                               const float* __restrict__ bfc) {
    __shared__ __align__(16) float As[16][64];
    __shared__ __align__(16) float Bs[16][64];
    int tid = threadIdx.x;
    int bm = blockIdx.y * 64, bn = blockIdx.x * 64;
    int ty = tid >> 4, tx = tid & 15;
    float acc[4][4];
#pragma unroll
    for (int i = 0; i < 4; i++)
#pragma unroll
        for (int j = 0; j < 4; j++) acc[i][j] = 0.f;

    int rA = tid >> 2;              // 0..63
    int kk = (tid & 3) * 4;         // 0,4,8,12
    int gr = bm + rA;
    const float* arow = feat_row(t, a, v, gr / MNODES, gr % MNODES);
    int rB = tid >> 4;              // 0..15
    int cB = (tid & 15) * 4;

    for (int k0 = 0; k0 < DIMF; k0 += 16) {
        float4 av = *(const float4*)(arow + k0 + kk);
        As[kk + 0][rA] = av.x; As[kk + 1][rA] = av.y;
        As[kk + 2][rA] = av.z; As[kk + 3][rA] = av.w;
        float4 bv = *(const float4*)(Wfc + (size_t)(k0 + rB) * GG + bn + cB);
        *(float4*)&Bs[rB][cB] = bv;
        __syncthreads();
#pragma unroll
        for (int k = 0; k < 16; k++) {
            float4 a4 = *(const float4*)&As[k][ty * 4];
            float4 b4 = *(const float4*)&Bs[k][tx * 4];
            acc[0][0] += a4.x * b4.x; acc[0][1] += a4.x * b4.y; acc[0][2] += a4.x * b4.z; acc[0][3] += a4.x * b4.w;
            acc[1][0] += a4.y * b4.x; acc[1][1] += a4.y * b4.y; acc[1][2] += a4.y * b4.z; acc[1][3] += a4.y * b4.w;
            acc[2][0] += a4.z * b4.x; acc[2][1] += a4.z * b4.y; acc[2][2] += a4.z * b4.z; acc[2][3] += a4.z * b4.w;
            acc[3][0] += a4.w * b4.x; acc[3][1] += a4.w * b4.y; acc[3][2] += a4.w * b4.z; acc[3][3] += a4.w * b4.w;
        }
        __syncthreads();
    }
#pragma unroll
    for (int i = 0; i < 4; i++) {
        int row = bm + ty * 4 + i;
#pragma unroll
        for (int j = 0; j < 4; j++) {
            int col = bn + tx * 4 + j;
            g_X[(size_t)row * GG + col] = acc[i][j] + bfc[col];
        }
    }
}

// ------------- distances + top-12 + incidence bitmask; 1 block per (d,row) -------------
__global__ void dist_topk_kernel(const float* __restrict__ t, const float* __restrict__ a,
                                 const float* __restrict__ v) {
    __shared__ float fr[DIMF];
    __shared__ float d2s[MNODES];
    __shared__ float rv[256];
    __shared__ int   ri[256];
    __shared__ int   chosen[KNN];
    __shared__ float s_sqr;
    int tid = threadIdx.x;
    int d = blockIdx.x / MNODES, r = blockIdx.x % MNODES;

    const float* frp = feat_row(t, a, v, d, r);
    float p = 0.f;
    for (int f = tid; f < DIMF; f += 256) { float x = frp[f]; fr[f] = x; p += x * x; }
    rv[tid] = p; __syncthreads();
    for (int s = 128; s; s >>= 1) { if (tid < s) rv[tid] += rv[tid + s]; __syncthreads(); }
    if (tid == 0) s_sqr = rv[0];
    __syncthreads();

    int wid = tid >> 5, lane = tid & 31;
    for (int j = wid; j < MNODES; j += 8) {
        const float* fj = feat_row(t, a, v, d, j);
        float dot = 0.f, s2 = 0.f;
        for (int f = lane; f < DIMF; f += 32) { float x = fj[f]; dot += fr[f] * x; s2 += x * x; }
#pragma unroll
        for (int o = 16; o; o >>= 1) {
            dot += __shfl_down_sync(0xffffffffu, dot, o);
            s2  += __shfl_down_sync(0xffffffffu, s2,  o);
        }
        if (lane == 0) {
            float dd = s_sqr + s2 - 2.f * dot;
            d2s[j] = dd > 0.f ? dd : 0.f;
        }
    }
    __syncthreads();

    // 12 argmin rounds, ties -> lowest index (matches top_k of -d2)
    for (int it = 0; it < KNN; ++it) {
        float vv = (tid < MNODES) ? d2s[tid] : 3.4e38f;
        rv[tid] = vv; ri[tid] = tid; __syncthreads();
        for (int s = 128; s; s >>= 1) {
            if (tid < s) {
                float ov = rv[tid + s]; int oi = ri[tid + s];
                if (ov < rv[tid] || (ov == rv[tid] && oi < ri[tid])) { rv[tid] = ov; ri[tid] = oi; }
            }
            __syncthreads();
        }
        if (tid == 0) { chosen[it] = ri[0]; d2s[ri[0]] = 3.4e38f; }
        __syncthreads();
    }

    if (tid == 0) {
        unsigned long long m0 = 0ull, m1 = 0ull, m2 = 0ull;
#pragma unroll
        for (int it = 0; it < KNN; ++it) {
            int n = chosen[it];
            if (n < 64) m0 |= 1ull << n;
            else if (n < 128) m1 |= 1ull << (n - 64);
            else m2 |= 1ull << (n - 128);
        }
        int u = r / 3;                // centrals u, u+64, u+128
        m0 |= 1ull << u; m1 |= 1ull << u; m2 |= 1ull << u;
        size_t base = (size_t)(d * MNODES + r) * 3;
        g_H[base] = m0; g_H[base + 1] = m1; g_H[base + 2] = m2;
    }
}

// ---------------- E[e] = mean over H-row member nodes of X ----------------
__global__ void edge_mean_kernel() {
    __shared__ int lst[MNODES];
    __shared__ int s_cnt;
    int tid = threadIdx.x;
    int d = blockIdx.x / MNODES, e = blockIdx.x % MNODES;
    if (tid == 0) {
        size_t base = (size_t)(d * MNODES + e) * 3;
        int c = 0;
        for (int wi = 0; wi < 3; wi++) {
            unsigned long long m = g_H[base + wi];
            while (m) { int b = __ffsll((long long)m) - 1; lst[c++] = wi * 64 + b; m &= m - 1; }
        }
        s_cnt = c;
    }
    __syncthreads();
    int cnt = s_cnt;
    float acc = 0.f;
    for (int i = 0; i < cnt; i++) acc += g_X[(size_t)(d * MNODES + lst[i]) * GG + tid];
    g_E[(size_t)(d * MNODES + e) * GG + tid] = acc / (float)cnt;
}

// ---------------- Y[n] = mean over edges containing n of E ----------------
__global__ void node_mean_kernel() {
    __shared__ int lst[MNODES];
    __shared__ unsigned char flag[MNODES];
    __shared__ int s_cnt;
    int tid = threadIdx.x;
    int d = blockIdx.x / MNODES, n = blockIdx.x % MNODES;
    int wi = n >> 6, bit = n & 63;
    if (tid < MNODES) {
        unsigned long long w = g_H[(size_t)(d * MNODES + tid) * 3 + wi];
        flag[tid] = (unsigned char)((w >> bit) & 1ull);
    }
    __syncthreads();
    if (tid == 0) {
        int c = 0;
        for (int e = 0; e < MNODES; e++) if (flag[e]) lst[c++] = e;
        s_cnt = c;
    }
    __syncthreads();
    int cnt = s_cnt;
    float acc = 0.f;
    for (int i = 0; i < cnt; i++) acc += g_E[(size_t)(d * MNODES + lst[i]) * GG + tid];
    g_Y[(size_t)(d * MNODES + n) * GG + tid] = acc / (float)cnt;
}

// ------------- out = relu(Y @ W_h + b_h), scattered to [4096,768] layout -------------
__global__ void wh_gemm_kernel(const float* __restrict__ Wh, const float* __restrict__ bh,
                               float* __restrict__ out) {
    __shared__ __align__(16) float As[16][64];
    __shared__ __align__(16) float Bs[16][64];
    int tid = threadIdx.x;
    int bm = blockIdx.y * 64, bn = blockIdx.x * 64;
    int ty = tid >> 4, tx = tid & 15;
    float acc[4][4];
#pragma unroll
    for (int i = 0; i < 4; i++)
#pragma unroll
        for (int j = 0; j < 4; j++) acc[i][j] = 0.f;

    int rA = tid >> 2;
    int kk = (tid & 3) * 4;
    const float* arow = g_Y + (size_t)(bm + rA) * GG;
    int rB = tid >> 4;
    int cB = (tid & 15) * 4;

    for (int k0 = 0; k0 < GG; k0 += 16) {
        float4 av = *(const float4*)(arow + k0 + kk);
        As[kk + 0][rA] = av.x; As[kk + 1][rA] = av.y;
        As[kk + 2][rA] = av.z; As[kk + 3][rA] = av.w;
        float4 bv = *(const float4*)(Wh + (size_t)(k0 + rB) * GG + bn + cB);
        *(float4*)&Bs[rB][cB] = bv;
        __syncthreads();
#pragma unroll
        for (int k = 0; k < 16; k++) {
            float4 a4 = *(const float4*)&As[k][ty * 4];
            float4 b4 = *(const float4*)&Bs[k][tx * 4];
            acc[0][0] += a4.x * b4.x; acc[0][1] += a4.x * b4.y; acc[0][2] += a4.x * b4.z; acc[0][3] += a4.x * b4.w;
            acc[1][0] += a4.y * b4.x; acc[1][1] += a4.y * b4.y; acc[1][2] += a4.y * b4.z; acc[1][3] += a4.y * b4.w;
            acc[2][0] += a4.z * b4.x; acc[2][1] += a4.z * b4.y; acc[2][2] += a4.z * b4.z; acc[2][3] += a4.z * b4.w;
            acc[3][0] += a4.w * b4.x; acc[3][1] += a4.w * b4.y; acc[3][2] += a4.w * b4.z; acc[3][3] += a4.w * b4.w;
        }
        __syncthreads();
    }
#pragma unroll
    for (int i = 0; i < 4; i++) {
        int row = bm + ty * 4 + i;
        int d = row / MNODES, n = row % MNODES;
        int mod = n >> 6, ii = n & 63;
        size_t obase = (size_t)(d * LL + ii) * 768 + (size_t)mod * GG;
#pragma unroll
        for (int j = 0; j < 4; j++) {
            int col = bn + tx * 4 + j;
            float vv = acc[i][j] + bh[col];
            out[obase + col] = vv > 0.f ? vv : 0.f;
        }
    }
}

// ---------------- row-normalize tn/an/vn into g_xn ----------------
__global__ void normalize_kernel(const float* __restrict__ out) {
    __shared__ float red[256];
    int tid = threadIdx.x;
    int mod = blockIdx.x / NROWS, i = blockIdx.x % NROWS;
    float x = out[(size_t)i * 768 + (size_t)mod * GG + tid];
    red[tid] = x * x; __syncthreads();
    for (int s = 128; s; s >>= 1) { if (tid < s) red[tid] += red[tid + s]; __syncthreads(); }
    float nrm = sqrtf(red[0]) + 1e-8f;
    g_xn[((size_t)mod * NROWS + i) * GG + tid] = x / nrm;
}

// ---------------- diagonal similarities for the 3 pairs ----------------
__global__ void diag_kernel() {
    __shared__ float red[256];
    int tid = threadIdx.x;
    int p = blockIdx.y;           // 0:(t,a) 1:(t,v) 2:(a,v)
    int i = blockIdx.x;
    int ma = (p == 2) ? 1 : 0;
    int mb = (p == 0) ? 1 : 2;
    float xa = g_xn[((size_t)ma * NROWS + i) * GG + tid];
    float xb = g_xn[((size_t)mb * NROWS + i) * GG + tid];
    red[tid] = xa * xb; __syncthreads();
    for (int s = 128; s; s >>= 1) { if (tid < s) red[tid] += red[tid + s]; __syncthreads(); }
    if (tid == 0) g_diag[(size_t)p * NROWS + i] = red[0] / TAUF;
}

// ---------------- streaming logsumexp of sim rows for 6 ordered pairs ----------------
__global__ void lse_kernel() {
    __shared__ float xs[64][33];
    __shared__ float ys[64][33];
    __shared__ float red[64][17];
    int tid = threadIdx.x;
    int itile = blockIdx.x;      // 0..63  (64 rows each)
    int mat   = blockIdx.y;      // 0..5 ordered pairs
    const int mx[6] = {0, 1, 0, 2, 1, 2};
    const int my[6] = {1, 0, 2, 0, 2, 1};
    const float* Xp = g_xn + (size_t)mx[mat] * NROWS * GG;
    const float* Yp = g_xn + (size_t)my[mat] * NROWS * GG;
    int i0 = itile * 64;
    int ty = tid >> 4, tx = tid & 15;
    float rs[4] = {0.f, 0.f, 0.f, 0.f};

    for (int jt = 0; jt < 64; ++jt) {
        int j0 = jt * 64;
        float acc[4][4];
#pragma unroll
        for (int ii = 0; ii < 4; ii++)
#pragma unroll
            for (int jj = 0; jj < 4; jj++) acc[ii][jj] = 0.f;

        for (int fc = 0; fc < GG; fc += 32) {
#pragma unroll
            for (int q = 0; q < 2; q++) {
                int id = tid + q * 256;
                int row = id >> 3, c4 = (id & 7) * 4;
                float4 xv = *(const float4*)(Xp + (size_t)(i0 + row) * GG + fc + c4);
                xs[row][c4] = xv.x; xs[row][c4 + 1] = xv.y; xs[row][c4 + 2] = xv.z; xs[row][c4 + 3] = xv.w;
                float4 yv = *(const float4*)(Yp + (size_t)(j0 + row) * GG + fc + c4);
                ys[row][c4] = yv.x; ys[row][c4 + 1] = yv.y; ys[row][c4 + 2] = yv.z; ys[row][c4 + 3] = yv.w;
            }
            __syncthreads();
#pragma unroll
            for (int k = 0; k < 32; k++) {
                float a0 = xs[ty * 4 + 0][k], a1 = xs[ty * 4 + 1][k];
                float a2 = xs[ty * 4 + 2][k], a3 = xs[ty * 4 + 3][k];
                float b0 = ys[tx * 4 + 0][k], b1 = ys[tx * 4 + 1][k];
                float b2 = ys[tx * 4 + 2][k], b3 = ys[tx * 4 + 3][k];
                acc[0][0] += a0 * b0; acc[0][1] += a0 * b1; acc[0][2] += a0 * b2; acc[0][3] += a0 * b3;
                acc[1][0] += a1 * b0; acc[1][1] += a1 * b1; acc[1][2] += a1 * b2; acc[1][3] += a1 * b3;
                acc[2][0] += a2 * b0; acc[2][1] += a2 * b1; acc[2][2] += a2 * b2; acc[2][3] += a2 * b3;
                acc[3][0] += a3 * b0; acc[3][1] += a3 * b1; acc[3][2] += a3 * b2; acc[3][3] += a3 * b3;
            }
            __syncthreads();
        }
#pragma unroll
        for (int ii = 0; ii < 4; ii++)
#pragma unroll
            for (int jj = 0; jj < 4; jj++)
                rs[ii] += __expf(acc[ii][jj] / TAUF);
    }
#pragma unroll
    for (int ii = 0; ii < 4; ii++) red[ty * 4 + ii][tx] = rs[ii];
    __syncthreads();
    if (tid < 64) {
        float s = 0.f;
        for (int x2 = 0; x2 < 16; x2++) s += red[tid][x2];
        g_lse[(size_t)mat * NROWS + i0 + tid] = logf(s);
    }
}

// ---------------- deterministic final reduction -> loss ----------------
__global__ void finalize_kernel(float* __restrict__ out, int out_size) {
    __shared__ double red[256];
    int tid = threadIdx.x;
    double sl = 0.0;
    for (int i = tid; i < 6 * NROWS; i += 256) sl += (double)g_lse[i];
    red[tid] = sl; __syncthreads();
    for (int s = 128; s; s >>= 1) { if (tid < s) red[tid] += red[tid + s]; __syncthreads(); }
    double SL = red[0]; __syncthreads();
    double sd = 0.0;
    for (int i = tid; i < 3 * NROWS; i += 256) sd += (double)g_diag[i];
    red[tid] = sd; __syncthreads();
    for (int s = 128; s; s >>= 1) { if (tid < s) red[tid] += red[tid + s]; __syncthreads(); }
    double SD = red[0];
    if (tid == 0 && out_size > NROWS * 768) {
        double loss = SL / (6.0 * NROWS) - SD / (3.0 * NROWS);
        out[NROWS * 768] = (float)loss;
    }
}

// ---------------- launch ----------------
extern "C" void kernel_launch(void* const* d_in, const int* in_sizes, int n_in,
                              void* d_out, int out_size) {
    const float* t   = (const float*)d_in[0];
    const float* a   = (const float*)d_in[1];
    const float* v   = (const float*)d_in[2];
    const float* Wfc = (const float*)d_in[3];
    const float* bfc = (const float*)d_in[4];
    const float* Wh  = (const float*)d_in[5];
    const float* bh  = (const float*)d_in[6];
    float* out = (float*)d_out;

    fc_gemm_kernel<<<dim3(GG / 64, (DD * MNODES) / 64), 256>>>(t, a, v, Wfc, bfc);
    dist_topk_kernel<<<DD * MNODES, 256>>>(t, a, v);
    edge_mean_kernel<<<DD * MNODES, 256>>>();
    node_mean_kernel<<<DD * MNODES, 256>>>();
    wh_gemm_kernel<<<dim3(GG / 64, (DD * MNODES) / 64), 256>>>(Wh, bh, out);
    normalize_kernel<<<3 * NROWS, 256>>>(out);
    diag_kernel<<<dim3(NROWS, 3), 256>>>();
    lse_kernel<<<dim3(64, 6), 256>>>();
    finalize_kernel<<<1, 256>>>(out, out_size);
}

// round 8
// speedup vs baseline: 2.2411x; 2.2411x over previous
#include <cuda_runtime.h>
#include <cuda_bf16.h>
#include <cstdint>
#include <math.h>

#define DD 64
#define LL 64
#define DIMF 512
#define GG 256
#define MNODES 192
#define KNN 12
#define NROWS 4096
#define TAUF 0.07f
#define KCAT 768   // bf16 split-GEMM K: [xh|xh|xl] . [yh|yl|yh]

// ---------------- device scratch (no allocations allowed) ----------------
__device__ float g_X[DD*MNODES*GG];              // fc output      [d,m,G]
__device__ float g_E[DD*MNODES*GG];              // edge features  [d,m,G]
__device__ float g_Y[DD*MNODES*GG];              // node features  [d,m,G]
__device__ unsigned long long g_H[DD*MNODES*3];  // incidence bitmask rows
__device__ float g_xn[3*NROWS*GG];               // normalized tn/an/vn (fp32, for diag)
__device__ __nv_bfloat16 g_xcatA[3ull*NROWS*KCAT]; // [xh|xh|xl] per row
__device__ __nv_bfloat16 g_xcatB[3ull*NROWS*KCAT]; // [yh|yl|yh] per row
__device__ float g_lsep[12*NROWS];               // partial row sums (6 mats x 2 j-halves)
__device__ float g_diag[3*NROWS];                // per-row diag sim (3 pairs)

// =====================  baseline-PTX helpers (no arch-specific instrs) =====================
#define CP_ASYNC16(dst, src) \
    asm volatile("cp.async.cg.shared.global [%0], [%1], 16;" :: "r"(dst), "l"(src) : "memory")
#define CP_COMMIT() asm volatile("cp.async.commit_group;" ::: "memory")
#define CP_WAIT1() asm volatile("cp.async.wait_group 1;" ::: "memory")
#define CP_WAIT0() asm volatile("cp.async.wait_group 0;" ::: "memory")

__device__ __forceinline__ uint32_t smem_to_u32(const void* smem_ptr) {
    uint32_t addr;
    asm("{ .reg .u64 tmp; cvta.to.shared.u64 tmp, %1; cvt.u32.u64 %0, tmp; }"
        : "=r"(addr) : "l"(smem_ptr));
    return addr;
}
__device__ __forceinline__ void ldsm_x4(uint32_t (&r)[4], uint32_t addr) {
    asm volatile("ldmatrix.sync.aligned.m8n8.x4.shared.b16 {%0,%1,%2,%3}, [%4];"
        : "=r"(r[0]), "=r"(r[1]), "=r"(r[2]), "=r"(r[3]) : "r"(addr));
}
__device__ __forceinline__ void ldsm_x2(uint32_t &r0, uint32_t &r1, uint32_t addr) {
    asm volatile("ldmatrix.sync.aligned.m8n8.x2.shared.b16 {%0,%1}, [%2];"
        : "=r"(r0), "=r"(r1) : "r"(addr));
}
__device__ __forceinline__ void mma16816(float (&d)[4], const uint32_t (&a)[4],
                                         uint32_t b0, uint32_t b1) {
    asm volatile("mma.sync.aligned.m16n8k16.row.col.f32.bf16.bf16.f32 "
        "{%0,%1,%2,%3}, {%4,%5,%6,%7}, {%8,%9}, {%0,%1,%2,%3};"
        : "+f"(d[0]), "+f"(d[1]), "+f"(d[2]), "+f"(d[3])
        : "r"(a[0]), "r"(a[1]), "r"(a[2]), "r"(a[3]), "r"(b0), "r"(b1));
}

// ===========================================================================

__device__ __forceinline__ const float* feat_row(const float* t, const float* a,
                                                 const float* v, int d, int n) {
    int mod = n >> 6;            // 0:t 1:a 2:v
    int i   = n & 63;
    const float* b = (mod == 0) ? t : (mod == 1) ? a : v;
    return b + (size_t)(d * LL + i) * DIMF;
}

__device__ __forceinline__ float wredsum(float x) {
#pragma unroll
    for (int o = 16; o; o >>= 1) x += __shfl_down_sync(0xffffffffu, x, o);
    return x;
}

// ---------------- X = feat @ W_fc + b_fc  (M=12288,K=512,N=256) ----------------
__global__ void fc_gemm_kernel(const float* __restrict__ t, const float* __restrict__ a,
                               const float* __restrict__ v, const float* __restrict__ Wfc,
                               const float* __restrict__ bfc) {
    __shared__ __align__(16) float As[16][64];
    __shared__ __align__(16) float Bs[16][64];
    int tid = threadIdx.x;
    int bm = blockIdx.y * 64, bn = blockIdx.x * 64;
    int ty = tid >> 4, tx = tid & 15;
    float acc[4][4];
#pragma unroll
    for (int i = 0; i < 4; i++)
#pragma unroll
        for (int j = 0; j < 4; j++) acc[i][j] = 0.f;

    int rA = tid >> 2;
    int kk = (tid & 3) * 4;
    int gr = bm + rA;
    const float* arow = feat_row(t, a, v, gr / MNODES, gr % MNODES);
    int rB = tid >> 4;
    int cB = (tid & 15) * 4;

    for (int k0 = 0; k0 < DIMF; k0 += 16) {
        float4 av = *(const float4*)(arow + k0 + kk);
        As[kk + 0][rA] = av.x; As[kk + 1][rA] = av.y;
        As[kk + 2][rA] = av.z; As[kk + 3][rA] = av.w;
        float4 bv = *(const float4*)(Wfc + (size_t)(k0 + rB) * GG + bn + cB);
        *(float4*)&Bs[rB][cB] = bv;
        __syncthreads();
#pragma unroll
        for (int k = 0; k < 16; k++) {
            float4 a4 = *(const float4*)&As[k][ty * 4];
            float4 b4 = *(const float4*)&Bs[k][tx * 4];
            acc[0][0] += a4.x * b4.x; acc[0][1] += a4.x * b4.y; acc[0][2] += a4.x * b4.z; acc[0][3] += a4.x * b4.w;
            acc[1][0] += a4.y * b4.x; acc[1][1] += a4.y * b4.y; acc[1][2] += a4.y * b4.z; acc[1][3] += a4.y * b4.w;
            acc[2][0] += a4.z * b4.x; acc[2][1] += a4.z * b4.y; acc[2][2] += a4.z * b4.z; acc[2][3] += a4.z * b4.w;
            acc[3][0] += a4.w * b4.x; acc[3][1] += a4.w * b4.y; acc[3][2] += a4.w * b4.z; acc[3][3] += a4.w * b4.w;
        }
        __syncthreads();
    }
#pragma unroll
    for (int i = 0; i < 4; i++) {
        int row = bm + ty * 4 + i;
#pragma unroll
        for (int j = 0; j < 4; j++) {
            int col = bn + tx * 4 + j;
            g_X[(size_t)row * GG + col] = acc[i][j] + bfc[col];
        }
    }
}

// ------ distances + top-12 + incidence; 1 block per (d, 16-row group) ------
__global__ void dist_topk_kernel(const float* __restrict__ t, const float* __restrict__ a,
                                 const float* __restrict__ v) {
    __shared__ float fr[16][DIMF];     // 32 KB
    __shared__ float sqr[16];
    __shared__ float d2s[16][MNODES];  // 12 KB
    int tid = threadIdx.x;
    int w = tid >> 5, lane = tid & 31;
    int d = blockIdx.x / 12, rg = blockIdx.x % 12;
    int r0 = rg * 16;

    // load 16 rows into smem
    for (int idx = tid; idx < 16 * DIMF; idx += 256) {
        int rr = idx >> 9, f = idx & (DIMF - 1);
        fr[rr][f] = feat_row(t, a, v, d, r0 + rr)[f];
    }
    __syncthreads();

    // per-row squared norms: warp w -> rows 2w, 2w+1
#pragma unroll
    for (int rr = 2 * w; rr < 2 * w + 2; rr++) {
        float s = 0.f;
        for (int f = lane; f < DIMF; f += 32) { float x = fr[rr][f]; s += x * x; }
        s = wredsum(s);
        if (lane == 0) sqr[rr] = s;
    }
    __syncthreads();

    // j-loop: each warp handles 2 j's per iteration (16 j's / block-iter)
    for (int it = 0; it < 12; ++it) {
        int j0 = it * 16 + w * 2;
        const float* f0 = feat_row(t, a, v, d, j0);
        const float* f1 = feat_row(t, a, v, d, j0 + 1);
        float dot0[16], dot1[16];
#pragma unroll
        for (int r = 0; r < 16; r++) { dot0[r] = 0.f; dot1[r] = 0.f; }
        float s20 = 0.f, s21 = 0.f;
        for (int f = lane; f < DIMF; f += 32) {
            float x0 = f0[f], x1 = f1[f];
            s20 += x0 * x0; s21 += x1 * x1;
#pragma unroll
            for (int r = 0; r < 16; r++) {
                float s = fr[r][f];
                dot0[r] += s * x0;
                dot1[r] += s * x1;
            }
        }
        s20 = wredsum(s20); s21 = wredsum(s21);
#pragma unroll
        for (int r = 0; r < 16; r++) {
            float dA = wredsum(dot0[r]);
            float dB = wredsum(dot1[r]);
            if (lane == 0) {
                float e0 = sqr[r] + s20 - 2.f * dA;
                float e1 = sqr[r] + s21 - 2.f * dB;
                d2s[r][j0]     = e0 > 0.f ? e0 : 0.f;
                d2s[r][j0 + 1] = e1 > 0.f ? e1 : 0.f;
            }
        }
    }
    __syncthreads();

    // top-12 per row (ties -> lowest index); warp w -> rows 2w, 2w+1
    for (int rr = 2 * w; rr < 2 * w + 2; rr++) {
        float vv[6];
#pragma unroll
        for (int q = 0; q < 6; q++) vv[q] = d2s[rr][lane + 32 * q];
        unsigned long long m0 = 0ull, m1 = 0ull, m2 = 0ull;
        for (int itk = 0; itk < KNN; ++itk) {
            float bv = vv[0]; int bi = lane;
#pragma unroll
            for (int q = 1; q < 6; q++) {
                if (vv[q] < bv) { bv = vv[q]; bi = lane + 32 * q; }
            }
#pragma unroll
            for (int o = 16; o; o >>= 1) {
                float ov = __shfl_down_sync(0xffffffffu, bv, o);
                int   oi = __shfl_down_sync(0xffffffffu, bi, o);
                if (ov < bv || (ov == bv && oi < bi)) { bv = ov; bi = oi; }
            }
            int n = __shfl_sync(0xffffffffu, bi, 0);
            if ((n & 31) == lane) vv[n >> 5] = 3.4e38f;
            if (n < 64) m0 |= 1ull << n;
            else if (n < 128) m1 |= 1ull << (n - 64);
            else m2 |= 1ull << (n - 128);
        }
        if (lane == 0) {
            int r = r0 + rr;
            int u = r / 3;
            m0 |= 1ull << u; m1 |= 1ull << u; m2 |= 1ull << u;
            size_t base = (size_t)(d * MNODES + r) * 3;
            g_H[base] = m0; g_H[base + 1] = m1; g_H[base + 2] = m2;
        }
    }
}

// ---------------- E[e] = mean over H-row member nodes of X ----------------
__global__ void edge_mean_kernel() {
    __shared__ int lst[MNODES];
    __shared__ int s_cnt;
    int tid = threadIdx.x;
    int d = blockIdx.x / MNODES, e = blockIdx.x % MNODES;
    if (tid == 0) {
        size_t base = (size_t)(d * MNODES + e) * 3;
        int c = 0;
        for (int wi = 0; wi < 3; wi++) {
            unsigned long long m = g_H[base + wi];
            while (m) { int b = __ffsll((long long)m) - 1; lst[c++] = wi * 64 + b; m &= m - 1; }
        }
        s_cnt = c;
    }
    __syncthreads();
    int cnt = s_cnt;
    float acc = 0.f;
    for (int i = 0; i < cnt; i++) acc += g_X[(size_t)(d * MNODES + lst[i]) * GG + tid];
    g_E[(size_t)(d * MNODES + e) * GG + tid] = acc / (float)cnt;
}

// ---------------- Y[n] = mean over edges containing n of E ----------------
__global__ void node_mean_kernel() {
    __shared__ int lst[MNODES];
    __shared__ unsigned char flag[MNODES];
    __shared__ int s_cnt;
    int tid = threadIdx.x;
    int d = blockIdx.x / MNODES, n = blockIdx.x % MNODES;
    int wi = n >> 6, bit = n & 63;
    if (tid < MNODES) {
        unsigned long long w = g_H[(size_t)(d * MNODES + tid) * 3 + wi];
        flag[tid] = (unsigned char)((w >> bit) & 1ull);
    }
    __syncthreads();
    if (tid == 0) {
        int c = 0;
        for (int e = 0; e < MNODES; e++) if (flag[e]) lst[c++] = e;
        s_cnt = c;
    }
    __syncthreads();
    int cnt = s_cnt;
    float acc = 0.f;
    for (int i = 0; i < cnt; i++) acc += g_E[(size_t)(d * MNODES + lst[i]) * GG + tid];
    g_Y[(size_t)(d * MNODES + n) * GG + tid] = acc / (float)cnt;
}

// ------------- out = relu(Y @ W_h + b_h), scattered to [4096,768] layout -------------
__global__ void wh_gemm_kernel(const float* __restrict__ Wh, const float* __restrict__ bh,
                               float* __restrict__ out) {
    __shared__ __align__(16) float As[16][64];
    __shared__ __align__(16) float Bs[16][64];
    int tid = threadIdx.x;
    int bm = blockIdx.y * 64, bn = blockIdx.x * 64;
    int ty = tid >> 4, tx = tid & 15;
    float acc[4][4];
#pragma unroll
    for (int i = 0; i < 4; i++)
#pragma unroll
        for (int j = 0; j < 4; j++) acc[i][j] = 0.f;

    int rA = tid >> 2;
    int kk = (tid & 3) * 4;
    const float* arow = g_Y + (size_t)(bm + rA) * GG;
    int rB = tid >> 4;
    int cB = (tid & 15) * 4;

    for (int k0 = 0; k0 < GG; k0 += 16) {
        float4 av = *(const float4*)(arow + k0 + kk);
        As[kk + 0][rA] = av.x; As[kk + 1][rA] = av.y;
        As[kk + 2][rA] = av.z; As[kk + 3][rA] = av.w;
        float4 bv = *(const float4*)(Wh + (size_t)(k0 + rB) * GG + bn + cB);
        *(float4*)&Bs[rB][cB] = bv;
        __syncthreads();
#pragma unroll
        for (int k = 0; k < 16; k++) {
            float4 a4 = *(const float4*)&As[k][ty * 4];
            float4 b4 = *(const float4*)&Bs[k][tx * 4];
            acc[0][0] += a4.x * b4.x; acc[0][1] += a4.x * b4.y; acc[0][2] += a4.x * b4.z; acc[0][3] += a4.x * b4.w;
            acc[1][0] += a4.y * b4.x; acc[1][1] += a4.y * b4.y; acc[1][2] += a4.y * b4.z; acc[1][3] += a4.y * b4.w;
            acc[2][0] += a4.z * b4.x; acc[2][1] += a4.z * b4.y; acc[2][2] += a4.z * b4.z; acc[2][3] += a4.z * b4.w;
            acc[3][0] += a4.w * b4.x; acc[3][1] += a4.w * b4.y; acc[3][2] += a4.w * b4.z; acc[3][3] += a4.w * b4.w;
        }
        __syncthreads();
    }
#pragma unroll
    for (int i = 0; i < 4; i++) {
        int row = bm + ty * 4 + i;
        int d = row / MNODES, n = row % MNODES;
        int mod = n >> 6, ii = n & 63;
        size_t obase = (size_t)(d * LL + ii) * 768 + (size_t)mod * GG;
#pragma unroll
        for (int j = 0; j < 4; j++) {
            int col = bn + tx * 4 + j;
            float vv = acc[i][j] + bh[col];
            out[obase + col] = vv > 0.f ? vv : 0.f;
        }
    }
}

// --------- row-normalize + build bf16 hi/lo split-K concat rows ---------
__global__ void normalize_kernel(const float* __restrict__ out) {
    __shared__ float red[256];
    int tid = threadIdx.x;
    int mod = blockIdx.x / NROWS, i = blockIdx.x % NROWS;
    float x = out[(size_t)i * 768 + (size_t)mod * GG + tid];
    red[tid] = x * x; __syncthreads();
    for (int s = 128; s; s >>= 1) { if (tid < s) red[tid] += red[tid + s]; __syncthreads(); }
    float nrm = sqrtf(red[0]) + 1e-8f;
    float xn = x / nrm;
    g_xn[((size_t)mod * NROWS + i) * GG + tid] = xn;
    __nv_bfloat16 xh = __float2bfloat16(xn);
    __nv_bfloat16 xl = __float2bfloat16(xn - __bfloat162float(xh));
    size_t rb = ((size_t)mod * NROWS + i) * KCAT;
    g_xcatA[rb + tid]       = xh;
    g_xcatA[rb + 256 + tid] = xh;
    g_xcatA[rb + 512 + tid] = xl;
    g_xcatB[rb + tid]       = xh;
    g_xcatB[rb + 256 + tid] = xl;
    g_xcatB[rb + 512 + tid] = xh;
}

// ---------------- diagonal similarities for the 3 pairs ----------------
__global__ void diag_kernel() {
    __shared__ float red[256];
    int tid = threadIdx.x;
    int p = blockIdx.y;           // 0:(t,a) 1:(t,v) 2:(a,v)
    int i = blockIdx.x;
    int ma = (p == 2) ? 1 : 0;
    int mb = (p == 0) ? 1 : 2;
    float xa = g_xn[((size_t)ma * NROWS + i) * GG + tid];
    float xb = g_xn[((size_t)mb * NROWS + i) * GG + tid];
    red[tid] = xa * xb; __syncthreads();
    for (int s = 128; s; s >>= 1) { if (tid < s) red[tid] += red[tid + s]; __syncthreads(); }
    if (tid == 0) g_diag[(size_t)p * NROWS + i] = red[0] / TAUF;
}

// ========= mma.sync bf16-split GEMM-LSE: A-tile resident, B streamed =========
// smem: A 128x768 bf16 (12 chunks of [128][64], swizzled)  = 196608 B
//       B double buffer 2 x [128][64] bf16                 =  32768 B
#define LSE2_ABYTES (128 * KCAT * 2)     // 196608
#define LSE2_BOFF   LSE2_ABYTES
#define LSE2_BCH    16384
#define LSE2_SMEM   (LSE2_ABYTES + 2 * LSE2_BCH)   // 229376

__global__ void __launch_bounds__(256, 1) lse_mma_kernel() {
    extern __shared__ char smem[];
    uint32_t sb = smem_to_u32(smem);
    int tid = threadIdx.x, lane = tid & 31, w = tid >> 5;
    int itile = blockIdx.x;          // 0..31
    int mat   = blockIdx.y;          // 0..5
    int jhalf = blockIdx.z;          // 0..1
    const int mx[6] = {0, 1, 0, 2, 1, 2};
    const int my[6] = {1, 0, 2, 0, 2, 1};
    const __nv_bfloat16* Xp = g_xcatA + (size_t)mx[mat] * NROWS * KCAT;
    const __nv_bfloat16* Yp = g_xcatB + (size_t)my[mat] * NROWS * KCAT;
    int i0 = itile * 128;

    // ---- load resident A tile (128 x 768 bf16) swizzled ----
#pragma unroll 4
    for (int q = 0; q < 48; q++) {
        int cid = q * 256 + tid;            // 16B chunk id, 0..12287
        int kc = cid >> 10;                  // chunk 0..11
        int rem = cid & 1023;
        int row = rem >> 3, c = rem & 7;
        uint4 vd = *(const uint4*)(Xp + (size_t)(i0 + row) * KCAT + kc * 64 + c * 8);
        *(uint4*)(smem + kc * 16384 + row * 128 + ((c ^ (row & 7)) << 4)) = vd;
    }
    __syncthreads();

    int wrow = (w & 3) * 32;    // warp row offset in 128-tile
    int wcol = (w >> 2) * 64;   // warp col offset in 128-tile

    const float kexp = 1.44269504088896340736f / TAUF;
    float rs[4] = {0.f, 0.f, 0.f, 0.f};

    // B issue helper (4 x 16B per thread per chunk)
    auto issueB = [&](int j0, int kc, int buf) {
#pragma unroll
        for (int q = 0; q < 4; q++) {
            int cid = q * 256 + tid;        // 0..1023
            int row = cid >> 3, c = cid & 7;
            const __nv_bfloat16* src = Yp + (size_t)(j0 + row) * KCAT + kc * 64 + c * 8;
            uint32_t dst = sb + LSE2_BOFF + buf * LSE2_BCH
                         + row * 128 + ((c ^ (row & 7)) << 4);
            CP_ASYNC16(dst, src);
        }
        CP_COMMIT();
    };

    int jt0 = jhalf * 16;
    issueB(jt0 * 128, 0, 0);

    for (int jt = 0; jt < 16; jt++) {
        int j0 = (jt0 + jt) * 128;
        float acc[2][8][4];
#pragma unroll
        for (int mt = 0; mt < 2; mt++)
#pragma unroll
            for (int nt = 0; nt < 8; nt++)
#pragma unroll
                for (int e = 0; e < 4; e++) acc[mt][nt][e] = 0.f;

        for (int kc = 0; kc < 12; kc++) {
            int gc = jt * 12 + kc;
            bool more = (kc < 11) || (jt < 15);
            if (more) {
                int nkc = (kc < 11) ? kc + 1 : 0;
                int nj0 = (kc < 11) ? j0 : j0 + 128;
                issueB(nj0, nkc, (gc + 1) & 1);
                CP_WAIT1();
            } else {
                CP_WAIT0();
            }
            __syncthreads();

            uint32_t abase = sb + kc * 16384;
            uint32_t bbase = sb + LSE2_BOFF + (gc & 1) * LSE2_BCH;
#pragma unroll
            for (int kq = 0; kq < 4; kq++) {
                uint32_t afr[2][4];
#pragma unroll
                for (int mt = 0; mt < 2; mt++) {
                    int row = wrow + mt * 16 + (lane & 7) + ((lane >> 3) & 1) * 8;
                    int c = kq * 2 + (lane >> 4);
                    ldsm_x4(afr[mt], abase + row * 128 + ((c ^ (row & 7)) << 4));
                }
#pragma unroll
                for (int nt = 0; nt < 8; nt++) {
                    int brow = wcol + nt * 8 + (lane & 7);
                    int bc = kq * 2 + ((lane >> 3) & 1);
                    uint32_t b0, b1;
                    ldsm_x2(b0, b1, bbase + brow * 128 + ((bc ^ (brow & 7)) << 4));
                    mma16816(acc[0][nt], afr[0], b0, b1);
                    mma16816(acc[1][nt], afr[1], b0, b1);
                }
            }
            __syncthreads();   // all reads of this buffer done before it is refilled
        }

        // epilogue: exp and accumulate per-thread row partials
#pragma unroll
        for (int mt = 0; mt < 2; mt++)
#pragma unroll
            for (int nt = 0; nt < 8; nt++) {
                rs[2 * mt + 0] += exp2f(acc[mt][nt][0] * kexp) + exp2f(acc[mt][nt][1] * kexp);
                rs[2 * mt + 1] += exp2f(acc[mt][nt][2] * kexp) + exp2f(acc[mt][nt][3] * kexp);
            }
    }

    // reduce across the 4 lanes sharing a row (distinct cols)
#pragma unroll
    for (int e = 0; e < 4; e++) {
        rs[e] += __shfl_xor_sync(0xffffffffu, rs[e], 1);
        rs[e] += __shfl_xor_sync(0xffffffffu, rs[e], 2);
    }

    float* rowsum = (float*)(smem + LSE2_BOFF);   // reuse B buffer space
    if (tid < 128) rowsum[tid] = 0.f;
    __syncthreads();
    if ((lane & 3) == 0) {
        int g = lane >> 2;
        atomicAdd(&rowsum[wrow + g],          rs[0]);   // 2 contributions/row -> deterministic
        atomicAdd(&rowsum[wrow + g + 8],      rs[1]);
        atomicAdd(&rowsum[wrow + 16 + g],     rs[2]);
        atomicAdd(&rowsum[wrow + 24 + g],     rs[3]);
    }
    __syncthreads();
    if (tid < 128)
        g_lsep[((size_t)mat * 2 + jhalf) * NROWS + i0 + tid] = rowsum[tid];
}

// ---------------- deterministic final reduction -> loss ----------------
__global__ void finalize_kernel(float* __restrict__ out, int out_size) {
    __shared__ double red[256];
    int tid = threadIdx.x;
    double sl = 0.0;
    for (int i = tid; i < 6 * NROWS; i += 256) {
        int m = i >> 12, r = i & (NROWS - 1);
        float s = g_lsep[((size_t)m * 2 + 0) * NROWS + r]
                + g_lsep[((size_t)m * 2 + 1) * NROWS + r];
        sl += (double)logf(s);
    }
    red[tid] = sl; __syncthreads();
    for (int s = 128; s; s >>= 1) { if (tid < s) red[tid] += red[tid + s]; __syncthreads(); }
    double SL = red[0]; __syncthreads();
    double sd = 0.0;
    for (int i = tid; i < 3 * NROWS; i += 256) sd += (double)g_diag[i];
    red[tid] = sd; __syncthreads();
    for (int s = 128; s; s >>= 1) { if (tid < s) red[tid] += red[tid + s]; __syncthreads(); }
    double SD = red[0];
    if (tid == 0 && out_size > NROWS * 768) {
        double loss = SL / (6.0 * NROWS) - SD / (3.0 * NROWS);
        out[NROWS * 768] = (float)loss;
    }
}

// ---------------- launch ----------------
extern "C" void kernel_launch(void* const* d_in, const int* in_sizes, int n_in,
                              void* d_out, int out_size) {
    const float* t   = (const float*)d_in[0];
    const float* a   = (const float*)d_in[1];
    const float* v   = (const float*)d_in[2];
    const float* Wfc = (const float*)d_in[3];
    const float* bfc = (const float*)d_in[4];
    const float* Wh  = (const float*)d_in[5];
    const float* bh  = (const float*)d_in[6];
    float* out = (float*)d_out;

    cudaFuncSetAttribute(lse_mma_kernel,
                         cudaFuncAttributeMaxDynamicSharedMemorySize, LSE2_SMEM);

    fc_gemm_kernel<<<dim3(GG / 64, (DD * MNODES) / 64), 256>>>(t, a, v, Wfc, bfc);
    dist_topk_kernel<<<DD * 12, 256>>>(t, a, v);
    edge_mean_kernel<<<DD * MNODES, 256>>>();
    node_mean_kernel<<<DD * MNODES, 256>>>();
    wh_gemm_kernel<<<dim3(GG / 64, (DD * MNODES) / 64), 256>>>(Wh, bh, out);
    normalize_kernel<<<3 * NROWS, 256>>>(out);
    diag_kernel<<<dim3(NROWS, 3), 256>>>();
    lse_mma_kernel<<<dim3(32, 6, 2), 256, LSE2_SMEM>>>();
    finalize_kernel<<<1, 256>>>(out, out_size);
}

// round 10
// speedup vs baseline: 2.3213x; 1.0358x over previous
#include <cuda_runtime.h>
#include <cuda_bf16.h>
#include <cstdint>
#include <math.h>

#define DD 64
#define LL 64
#define DIMF 512
#define GG 256
#define MNODES 192
#define KNN 12
#define NROWS 4096
#define TAUF 0.07f
#define KCAT 768   // bf16 split-GEMM K: [xh|xh|xl] . [yh|yl|yh]
#define LSE_GRID 148
#define LSE_ITEMS 1536   // 6 mats x 32 itiles x 8 j-eighths

// ---------------- device scratch (no allocations allowed) ----------------
__device__ float g_X[DD*MNODES*GG];              // fc output      [d,m,G]
__device__ float g_Y[DD*MNODES*GG];              // node features  [d,m,G]
__device__ unsigned long long g_H[DD*MNODES*3];  // incidence bitmask rows
__device__ float g_xn[3*NROWS*GG];               // normalized tn/an/vn (fp32, for diag)
__device__ __nv_bfloat16 g_xcatA[3ull*NROWS*KCAT]; // [xh|xh|xl] per row
__device__ __nv_bfloat16 g_xcatB[3ull*NROWS*KCAT]; // [yh|yl|yh] per row
__device__ float g_lsep[6*8*NROWS];              // partial row sums (mat x jq)
__device__ float g_diag[3*NROWS];                // per-row diag sim (3 pairs)
__device__ unsigned int g_item_ctr;              // lse work-steal counter

// =====================  baseline-PTX helpers =====================
#define CP_ASYNC16(dst, src) \
    asm volatile("cp.async.cg.shared.global [%0], [%1], 16;" :: "r"(dst), "l"(src) : "memory")
#define CP_COMMIT() asm volatile("cp.async.commit_group;" ::: "memory")
#define CP_WAIT1() asm volatile("cp.async.wait_group 1;" ::: "memory")
#define CP_WAIT0() asm volatile("cp.async.wait_group 0;" ::: "memory")

__device__ __forceinline__ uint32_t smem_to_u32(const void* smem_ptr) {
    uint32_t addr;
    asm("{ .reg .u64 tmp; cvta.to.shared.u64 tmp, %1; cvt.u32.u64 %0, tmp; }"
        : "=r"(addr) : "l"(smem_ptr));
    return addr;
}
__device__ __forceinline__ void ldsm_x4(uint32_t (&r)[4], uint32_t addr) {
    asm volatile("ldmatrix.sync.aligned.m8n8.x4.shared.b16 {%0,%1,%2,%3}, [%4];"
        : "=r"(r[0]), "=r"(r[1]), "=r"(r[2]), "=r"(r[3]) : "r"(addr));
}
__device__ __forceinline__ void mma16816(float (&d)[4], const uint32_t (&a)[4],
                                         uint32_t b0, uint32_t b1) {
    asm volatile("mma.sync.aligned.m16n8k16.row.col.f32.bf16.bf16.f32 "
        "{%0,%1,%2,%3}, {%4,%5,%6,%7}, {%8,%9}, {%0,%1,%2,%3};"
        : "+f"(d[0]), "+f"(d[1]), "+f"(d[2]), "+f"(d[3])
        : "r"(a[0]), "r"(a[1]), "r"(a[2]), "r"(a[3]), "r"(b0), "r"(b1));
}

// ===========================================================================

__device__ __forceinline__ const float* feat_row(const float* t, const float* a,
                                                 const float* v, int d, int n) {
    int mod = n >> 6;            // 0:t 1:a 2:v
    int i   = n & 63;
    const float* b = (mod == 0) ? t : (mod == 1) ? a : v;
    return b + (size_t)(d * LL + i) * DIMF;
}

__device__ __forceinline__ float wredsum(float x) {
#pragma unroll
    for (int o = 16; o; o >>= 1) x += __shfl_down_sync(0xffffffffu, x, o);
    return x;
}

// ---------------- X = feat @ W_fc + b_fc  (M=12288,K=512,N=256) ----------------
__global__ void fc_gemm_kernel(const float* __restrict__ t, const float* __restrict__ a,
                               const float* __restrict__ v, const float* __restrict__ Wfc,
                               const float* __restrict__ bfc) {
    __shared__ __align__(16) float As[16][64];
    __shared__ __align__(16) float Bs[16][64];
    int tid = threadIdx.x;
    int bm = blockIdx.y * 64, bn = blockIdx.x * 64;
    int ty = tid >> 4, tx = tid & 15;
    float acc[4][4];
#pragma unroll
    for (int i = 0; i < 4; i++)
#pragma unroll
        for (int j = 0; j < 4; j++) acc[i][j] = 0.f;

    int rA = tid >> 2;
    int kk = (tid & 3) * 4;
    int gr = bm + rA;
    const float* arow = feat_row(t, a, v, gr / MNODES, gr % MNODES);
    int rB = tid >> 4;
    int cB = (tid & 15) * 4;

    for (int k0 = 0; k0 < DIMF; k0 += 16) {
        float4 av = *(const float4*)(arow + k0 + kk);
        As[kk + 0][rA] = av.x; As[kk + 1][rA] = av.y;
        As[kk + 2][rA] = av.z; As[kk + 3][rA] = av.w;
        float4 bv = *(const float4*)(Wfc + (size_t)(k0 + rB) * GG + bn + cB);
        *(float4*)&Bs[rB][cB] = bv;
        __syncthreads();
#pragma unroll
        for (int k = 0; k < 16; k++) {
            float4 a4 = *(const float4*)&As[k][ty * 4];
            float4 b4 = *(const float4*)&Bs[k][tx * 4];
            acc[0][0] += a4.x * b4.x; acc[0][1] += a4.x * b4.y; acc[0][2] += a4.x * b4.z; acc[0][3] += a4.x * b4.w;
            acc[1][0] += a4.y * b4.x; acc[1][1] += a4.y * b4.y; acc[1][2] += a4.y * b4.z; acc[1][3] += a4.y * b4.w;
            acc[2][0] += a4.z * b4.x; acc[2][1] += a4.z * b4.y; acc[2][2] += a4.z * b4.z; acc[2][3] += a4.z * b4.w;
            acc[3][0] += a4.w * b4.x; acc[3][1] += a4.w * b4.y; acc[3][2] += a4.w * b4.z; acc[3][3] += a4.w * b4.w;
        }
        __syncthreads();
    }
#pragma unroll
    for (int i = 0; i < 4; i++) {
        int row = bm + ty * 4 + i;
#pragma unroll
        for (int j = 0; j < 4; j++) {
            int col = bn + tx * 4 + j;
            g_X[(size_t)row * GG + col] = acc[i][j] + bfc[col];
        }
    }
}

// ------ distances + top-12 + incidence; 1 block per (d, 16-row group) ------
__global__ void dist_topk_kernel(const float* __restrict__ t, const float* __restrict__ a,
                                 const float* __restrict__ v) {
    __shared__ float fr[16][DIMF];     // 32 KB
    __shared__ float sqr[16];
    __shared__ float d2s[16][MNODES];  // 12 KB
    int tid = threadIdx.x;
    int w = tid >> 5, lane = tid & 31;
    int d = blockIdx.x / 12, rg = blockIdx.x % 12;
    int r0 = rg * 16;

    for (int idx = tid; idx < 16 * DIMF; idx += 256) {
        int rr = idx >> 9, f = idx & (DIMF - 1);
        fr[rr][f] = feat_row(t, a, v, d, r0 + rr)[f];
    }
    __syncthreads();

#pragma unroll
    for (int rr = 2 * w; rr < 2 * w + 2; rr++) {
        float s = 0.f;
        for (int f = lane; f < DIMF; f += 32) { float x = fr[rr][f]; s += x * x; }
        s = wredsum(s);
        if (lane == 0) sqr[rr] = s;
    }
    __syncthreads();

    for (int it = 0; it < 12; ++it) {
        int j0 = it * 16 + w * 2;
        const float* f0 = feat_row(t, a, v, d, j0);
        const float* f1 = feat_row(t, a, v, d, j0 + 1);
        float dot0[16], dot1[16];
#pragma unroll
        for (int r = 0; r < 16; r++) { dot0[r] = 0.f; dot1[r] = 0.f; }
        float s20 = 0.f, s21 = 0.f;
        for (int f = lane; f < DIMF; f += 32) {
            float x0 = f0[f], x1 = f1[f];
            s20 += x0 * x0; s21 += x1 * x1;
#pragma unroll
            for (int r = 0; r < 16; r++) {
                float s = fr[r][f];
                dot0[r] += s * x0;
                dot1[r] += s * x1;
            }
        }
        s20 = wredsum(s20); s21 = wredsum(s21);
#pragma unroll
        for (int r = 0; r < 16; r++) {
            float dA = wredsum(dot0[r]);
            float dB = wredsum(dot1[r]);
            if (lane == 0) {
                float e0 = sqr[r] + s20 - 2.f * dA;
                float e1 = sqr[r] + s21 - 2.f * dB;
                d2s[r][j0]     = e0 > 0.f ? e0 : 0.f;
                d2s[r][j0 + 1] = e1 > 0.f ? e1 : 0.f;
            }
        }
    }
    __syncthreads();

    for (int rr = 2 * w; rr < 2 * w + 2; rr++) {
        float vv[6];
#pragma unroll
        for (int q = 0; q < 6; q++) vv[q] = d2s[rr][lane + 32 * q];
        unsigned long long m0 = 0ull, m1 = 0ull, m2 = 0ull;
        for (int itk = 0; itk < KNN; ++itk) {
            float bv = vv[0]; int bi = lane;
#pragma unroll
            for (int q = 1; q < 6; q++) {
                if (vv[q] < bv) { bv = vv[q]; bi = lane + 32 * q; }
            }
#pragma unroll
            for (int o = 16; o; o >>= 1) {
                float ov = __shfl_down_sync(0xffffffffu, bv, o);
                int   oi = __shfl_down_sync(0xffffffffu, bi, o);
                if (ov < bv || (ov == bv && oi < bi)) { bv = ov; bi = oi; }
            }
            int n = __shfl_sync(0xffffffffu, bi, 0);
            if ((n & 31) == lane) vv[n >> 5] = 3.4e38f;
            if (n < 64) m0 |= 1ull << n;
            else if (n < 128) m1 |= 1ull << (n - 64);
            else m2 |= 1ull << (n - 128);
        }
        if (lane == 0) {
            int r = r0 + rr;
            int u = r / 3;
            m0 |= 1ull << u; m1 |= 1ull << u; m2 |= 1ull << u;
            size_t base = (size_t)(d * MNODES + r) * 3;
            g_H[base] = m0; g_H[base + 1] = m1; g_H[base + 2] = m2;
        }
    }
}

// ===== fused hypergraph conv: E = H@X/deg_e, Y = H^T@E/deg_v, all in smem =====
// block = (dialogue, 64-col G-slice). smem: Xs 48K + Es 48K + Hs 4.5K + Ht32 4.5K
#define HC_XS    0
#define HC_ES    49152
#define HC_HS    98304
#define HC_HT    102912
#define HC_SMEM  107520

__global__ void __launch_bounds__(256) hyperconv_kernel() {
    extern __shared__ char hsm[];
    float* Xs = (float*)(hsm + HC_XS);                       // [192][64]
    float* Es = (float*)(hsm + HC_ES);                       // [192][64]
    unsigned long long* Hs = (unsigned long long*)(hsm + HC_HS);  // [192][3]
    uint32_t* Ht = (uint32_t*)(hsm + HC_HT);                 // [192][6] edge-bits per node
    int tid = threadIdx.x, lane = tid & 31, w = tid >> 5;
    int d = blockIdx.x, gs = blockIdx.y * 64;

    for (int idx = tid; idx < MNODES * 64; idx += 256) {
        int r = idx >> 6, c = idx & 63;
        Xs[idx] = g_X[(size_t)(d * MNODES + r) * GG + gs + c];
    }
    for (int idx = tid; idx < MNODES * 3; idx += 256)
        Hs[idx] = g_H[(size_t)d * (MNODES * 3) + idx];
    __syncthreads();

    // transpose H into per-node edge bitmasks via warp ballots (warps 0..5)
    if (w < 6) {
        int e = w * 32 + lane;
        unsigned long long r0 = Hs[e * 3 + 0], r1 = Hs[e * 3 + 1], r2 = Hs[e * 3 + 2];
        for (int n = 0; n < 64; n++) {
            uint32_t b0 = __ballot_sync(0xffffffffu, (r0 >> n) & 1ull);
            uint32_t b1 = __ballot_sync(0xffffffffu, (r1 >> n) & 1ull);
            uint32_t b2 = __ballot_sync(0xffffffffu, (r2 >> n) & 1ull);
            if (lane == 0) {
                Ht[n * 6 + w]         = b0;
                Ht[(n + 64) * 6 + w]  = b1;
                Ht[(n + 128) * 6 + w] = b2;
            }
        }
    }
    __syncthreads();

    // E[e] = mean over member nodes (warp-uniform mask iteration)
    for (int e = w; e < MNODES; e += 8) {
        float a0 = 0.f, a1 = 0.f;
        int c = 0;
#pragma unroll
        for (int wi = 0; wi < 3; wi++) {
            unsigned long long m = Hs[e * 3 + wi];
            c += __popcll(m);
            while (m) {
                int b = __ffsll((long long)m) - 1; m &= m - 1;
                int n = wi * 64 + b;
                a0 += Xs[n * 64 + lane];
                a1 += Xs[n * 64 + lane + 32];
            }
        }
        float fc2 = (float)c;
        Es[e * 64 + lane]      = a0 / fc2;
        Es[e * 64 + lane + 32] = a1 / fc2;
    }
    __syncthreads();

    // Y[n] = mean over edges containing n
    for (int n = w; n < MNODES; n += 8) {
        float a0 = 0.f, a1 = 0.f;
        int c = 0;
#pragma unroll
        for (int wi = 0; wi < 6; wi++) {
            uint32_t m = Ht[n * 6 + wi];
            c += __popc(m);
            while (m) {
                int b = __ffs((int)m) - 1; m &= m - 1;
                int e = wi * 32 + b;
                a0 += Es[e * 64 + lane];
                a1 += Es[e * 64 + lane + 32];
            }
        }
        float fc2 = (float)c;
        size_t o = (size_t)(d * MNODES + n) * GG + gs;
        g_Y[o + lane]      = a0 / fc2;
        g_Y[o + lane + 32] = a1 / fc2;
    }
}

// ------------- out = relu(Y @ W_h + b_h), scattered to [4096,768] layout -------------
__global__ void wh_gemm_kernel(const float* __restrict__ Wh, const float* __restrict__ bh,
                               float* __restrict__ out) {
    __shared__ __align__(16) float As[16][64];
    __shared__ __align__(16) float Bs[16][64];
    int tid = threadIdx.x;
    int bm = blockIdx.y * 64, bn = blockIdx.x * 64;
    int ty = tid >> 4, tx = tid & 15;
    float acc[4][4];
#pragma unroll
    for (int i = 0; i < 4; i++)
#pragma unroll
        for (int j = 0; j < 4; j++) acc[i][j] = 0.f;

    int rA = tid >> 2;
    int kk = (tid & 3) * 4;
    const float* arow = g_Y + (size_t)(bm + rA) * GG;
    int rB = tid >> 4;
    int cB = (tid & 15) * 4;

    for (int k0 = 0; k0 < GG; k0 += 16) {
        float4 av = *(const float4*)(arow + k0 + kk);
        As[kk + 0][rA] = av.x; As[kk + 1][rA] = av.y;
        As[kk + 2][rA] = av.z; As[kk + 3][rA] = av.w;
        float4 bv = *(const float4*)(Wh + (size_t)(k0 + rB) * GG + bn + cB);
        *(float4*)&Bs[rB][cB] = bv;
        __syncthreads();
#pragma unroll
        for (int k = 0; k < 16; k++) {
            float4 a4 = *(const float4*)&As[k][ty * 4];
            float4 b4 = *(const float4*)&Bs[k][tx * 4];
            acc[0][0] += a4.x * b4.x; acc[0][1] += a4.x * b4.y; acc[0][2] += a4.x * b4.z; acc[0][3] += a4.x * b4.w;
            acc[1][0] += a4.y * b4.x; acc[1][1] += a4.y * b4.y; acc[1][2] += a4.y * b4.z; acc[1][3] += a4.y * b4.w;
            acc[2][0] += a4.z * b4.x; acc[2][1] += a4.z * b4.y; acc[2][2] += a4.z * b4.z; acc[2][3] += a4.z * b4.w;
            acc[3][0] += a4.w * b4.x; acc[3][1] += a4.w * b4.y; acc[3][2] += a4.w * b4.z; acc[3][3] += a4.w * b4.w;
        }
        __syncthreads();
    }
#pragma unroll
    for (int i = 0; i < 4; i++) {
        int row = bm + ty * 4 + i;
        int d = row / MNODES, n = row % MNODES;
        int mod = n >> 6, ii = n & 63;
        size_t obase = (size_t)(d * LL + ii) * 768 + (size_t)mod * GG;
#pragma unroll
        for (int j = 0; j < 4; j++) {
            int col = bn + tx * 4 + j;
            float vv = acc[i][j] + bh[col];
            out[obase + col] = vv > 0.f ? vv : 0.f;
        }
    }
}

// --------- row-normalize + build bf16 hi/lo split-K concat rows ---------
__global__ void normalize_kernel(const float* __restrict__ out) {
    __shared__ float red[256];
    int tid = threadIdx.x;
    int mod = blockIdx.x / NROWS, i = blockIdx.x % NROWS;
    float x = out[(size_t)i * 768 + (size_t)mod * GG + tid];
    red[tid] = x * x; __syncthreads();
    for (int s = 128; s; s >>= 1) { if (tid < s) red[tid] += red[tid + s]; __syncthreads(); }
    float nrm = sqrtf(red[0]) + 1e-8f;
    float xn = x / nrm;
    g_xn[((size_t)mod * NROWS + i) * GG + tid] = xn;
    __nv_bfloat16 xh = __float2bfloat16(xn);
    __nv_bfloat16 xl = __float2bfloat16(xn - __bfloat162float(xh));
    size_t rb = ((size_t)mod * NROWS + i) * KCAT;
    g_xcatA[rb + tid]       = xh;
    g_xcatA[rb + 256 + tid] = xh;
    g_xcatA[rb + 512 + tid] = xl;
    g_xcatB[rb + tid]       = xh;
    g_xcatB[rb + 256 + tid] = xl;
    g_xcatB[rb + 512 + tid] = xh;
}

// ---------------- diagonal similarities + lse counter reset ----------------
__global__ void diag_kernel() {
    __shared__ float red[256];
    int tid = threadIdx.x;
    int p = blockIdx.y;
    int i = blockIdx.x;
    if (p == 0 && i == 0 && tid == 0) g_item_ctr = LSE_GRID;   // reset work-steal counter
    int ma = (p == 2) ? 1 : 0;
    int mb = (p == 0) ? 1 : 2;
    float xa = g_xn[((size_t)ma * NROWS + i) * GG + tid];
    float xb = g_xn[((size_t)mb * NROWS + i) * GG + tid];
    red[tid] = xa * xb; __syncthreads();
    for (int s = 128; s; s >>= 1) { if (tid < s) red[tid] += red[tid + s]; __syncthreads(); }
    if (tid == 0) g_diag[(size_t)p * NROWS + i] = red[0] / TAUF;
}

// ========= persistent mma.sync GEMM-LSE with work stealing =========
// smem: A 128x768 bf16 (12 chunks of [128][64], swizzled) + B double buffer
#define LSE2_ABYTES (128 * KCAT * 2)     // 196608
#define LSE2_BOFF   LSE2_ABYTES
#define LSE2_BCH    16384
#define LSE2_SMEM   (LSE2_ABYTES + 2 * LSE2_BCH)   // 229376

__global__ void __launch_bounds__(256, 1) lse_mma_kernel() {
    extern __shared__ char smem[];
    __shared__ int s_item;
    uint32_t sb = smem_to_u32(smem);
    int tid = threadIdx.x, lane = tid & 31, w = tid >> 5;
    const int mx[6] = {0, 1, 0, 2, 1, 2};
    const int my[6] = {1, 0, 2, 0, 2, 1};
    int wrow = (w & 3) * 32;
    int wcol = (w >> 2) * 64;
    const float kexp = 1.44269504088896340736f / TAUF;

    int item = blockIdx.x;
    int aid = -1;
    const __nv_bfloat16* Yp = nullptr;

    auto issueB = [&](int j0, int kc, int buf) {
#pragma unroll
        for (int q = 0; q < 4; q++) {
            int cid = q * 256 + tid;        // 0..1023
            int row = cid >> 3, c = cid & 7;
            const __nv_bfloat16* src = Yp + (size_t)(j0 + row) * KCAT + kc * 64 + c * 8;
            uint32_t dst = sb + LSE2_BOFF + buf * LSE2_BCH
                         + row * 128 + ((c ^ (row & 7)) << 4);
            CP_ASYNC16(dst, src);
        }
        CP_COMMIT();
    };

    while (item < LSE_ITEMS) {
        int mat = item >> 8;             // /256
        int rem = item & 255;
        int itile = rem >> 3, jq = rem & 7;
        int i0 = itile * 128;
        Yp = g_xcatB + (size_t)my[mat] * NROWS * KCAT;

        int na = item >> 3;
        if (na != aid) {                 // (re)load resident A tile
            const __nv_bfloat16* Xp = g_xcatA + (size_t)mx[mat] * NROWS * KCAT;
#pragma unroll 4
            for (int q = 0; q < 48; q++) {
                int cid = q * 256 + tid;
                int kc = cid >> 10;
                int r2 = cid & 1023;
                int row = r2 >> 3, c = r2 & 7;
                uint4 vd = *(const uint4*)(Xp + (size_t)(i0 + row) * KCAT + kc * 64 + c * 8);
                *(uint4*)(smem + kc * 16384 + row * 128 + ((c ^ (row & 7)) << 4)) = vd;
            }
            __syncthreads();
            aid = na;
        }

        float rs[4] = {0.f, 0.f, 0.f, 0.f};
        issueB((jq * 4) * 128, 0, 0);

        for (int jt = 0; jt < 4; jt++) {
            int j0 = (jq * 4 + jt) * 128;
            float acc[2][8][4];
#pragma unroll
            for (int mt = 0; mt < 2; mt++)
#pragma unroll
                for (int nt = 0; nt < 8; nt++)
#pragma unroll
                    for (int e = 0; e < 4; e++) acc[mt][nt][e] = 0.f;

            for (int kc = 0; kc < 12; kc++) {
                int gi = jt * 12 + kc;
                bool more = (kc < 11) || (jt < 3);
                if (more) {
                    int nkc = (kc < 11) ? kc + 1 : 0;
                    int nj0 = (kc < 11) ? j0 : j0 + 128;
                    issueB(nj0, nkc, (gi + 1) & 1);
                    CP_WAIT1();
                } else {
                    CP_WAIT0();
                }
                __syncthreads();

                uint32_t abase = sb + kc * 16384;
                uint32_t bbase = sb + LSE2_BOFF + (gi & 1) * LSE2_BCH;
#pragma unroll
                for (int kq = 0; kq < 4; kq++) {
                    uint32_t afr[2][4];
#pragma unroll
                    for (int mt = 0; mt < 2; mt++) {
                        int row = wrow + mt * 16 + (lane & 7) + ((lane >> 3) & 1) * 8;
                        int c = kq * 2 + (lane >> 4);
                        ldsm_x4(afr[mt], abase + row * 128 + ((c ^ (row & 7)) << 4));
                    }
#pragma unroll
                    for (int nt = 0; nt < 8; nt += 2) {
                        int quad = lane >> 3;
                        int brow = wcol + (nt + (quad >> 1)) * 8 + (lane & 7);
                        int bc = kq * 2 + (quad & 1);
                        uint32_t bf[4];
                        ldsm_x4(bf, bbase + brow * 128 + ((bc ^ (brow & 7)) << 4));
                        mma16816(acc[0][nt],     afr[0], bf[0], bf[1]);
                        mma16816(acc[1][nt],     afr[1], bf[0], bf[1]);
                        mma16816(acc[0][nt + 1], afr[0], bf[2], bf[3]);
                        mma16816(acc[1][nt + 1], afr[1], bf[2], bf[3]);
                    }
                }
                __syncthreads();
            }

#pragma unroll
            for (int mt = 0; mt < 2; mt++)
#pragma unroll
                for (int nt = 0; nt < 8; nt++) {
                    rs[2 * mt + 0] += exp2f(acc[mt][nt][0] * kexp) + exp2f(acc[mt][nt][1] * kexp);
                    rs[2 * mt + 1] += exp2f(acc[mt][nt][2] * kexp) + exp2f(acc[mt][nt][3] * kexp);
                }
        }

        // reduce across 4 lanes sharing a row (distinct cols)
#pragma unroll
        for (int e = 0; e < 4; e++) {
            rs[e] += __shfl_xor_sync(0xffffffffu, rs[e], 1);
            rs[e] += __shfl_xor_sync(0xffffffffu, rs[e], 2);
        }

        // deterministic 2-slot reduction (no float atomics)
        float* rs2 = (float*)(smem + LSE2_BOFF);   // B buffers idle here
        if ((lane & 3) == 0) {
            int g = lane >> 2;
            int grp = (w >> 2) * 128;
            rs2[grp + wrow + g]          = rs[0];
            rs2[grp + wrow + g + 8]      = rs[1];
            rs2[grp + wrow + 16 + g]     = rs[2];
            rs2[grp + wrow + 24 + g]     = rs[3];
        }
        __syncthreads();
        if (tid < 128)
            g_lsep[((size_t)mat * 8 + jq) * NROWS + i0 + tid] = rs2[tid] + rs2[128 + tid];

        if (tid == 0) s_item = (int)atomicAdd(&g_item_ctr, 1u);
        __syncthreads();
        item = s_item;
    }
}

// ---------------- deterministic final reduction -> loss ----------------
__global__ void finalize_kernel(float* __restrict__ out, int out_size) {
    __shared__ double red[256];
    int tid = threadIdx.x;
    double sl = 0.0;
    for (int i = tid; i < 6 * NROWS; i += 256) {
        int m = i >> 12, r = i & (NROWS - 1);
        float s = 0.f;
#pragma unroll
        for (int jq = 0; jq < 8; jq++)
            s += g_lsep[((size_t)m * 8 + jq) * NROWS + r];
        sl += (double)logf(s);
    }
    red[tid] = sl; __syncthreads();
    for (int s = 128; s; s >>= 1) { if (tid < s) red[tid] += red[tid + s]; __syncthreads(); }
    double SL = red[0]; __syncthreads();
    double sd = 0.0;
    for (int i = tid; i < 3 * NROWS; i += 256) sd += (double)g_diag[i];
    red[tid] = sd; __syncthreads();
    for (int s = 128; s; s >>= 1) { if (tid < s) red[tid] += red[tid + s]; __syncthreads(); }
    double SD = red[0];
    if (tid == 0 && out_size > NROWS * 768) {
        double loss = SL / (6.0 * NROWS) - SD / (3.0 * NROWS);
        out[NROWS * 768] = (float)loss;
    }
}

// ---------------- launch ----------------
extern "C" void kernel_launch(void* const* d_in, const int* in_sizes, int n_in,
                              void* d_out, int out_size) {
    const float* t   = (const float*)d_in[0];
    const float* a   = (const float*)d_in[1];
    const float* v   = (const float*)d_in[2];
    const float* Wfc = (const float*)d_in[3];
    const float* bfc = (const float*)d_in[4];
    const float* Wh  = (const float*)d_in[5];
    const float* bh  = (const float*)d_in[6];
    float* out = (float*)d_out;

    cudaFuncSetAttribute(lse_mma_kernel,
                         cudaFuncAttributeMaxDynamicSharedMemorySize, LSE2_SMEM);
    cudaFuncSetAttribute(hyperconv_kernel,
                         cudaFuncAttributeMaxDynamicSharedMemorySize, HC_SMEM);

    fc_gemm_kernel<<<dim3(GG / 64, (DD * MNODES) / 64), 256>>>(t, a, v, Wfc, bfc);
    dist_topk_kernel<<<DD * 12, 256>>>(t, a, v);
    hyperconv_kernel<<<dim3(DD, 4), 256, HC_SMEM>>>();
    wh_gemm_kernel<<<dim3(GG / 64, (DD * MNODES) / 64), 256>>>(Wh, bh, out);
    normalize_kernel<<<3 * NROWS, 256>>>(out);
    diag_kernel<<<dim3(NROWS, 3), 256>>>();
    lse_mma_kernel<<<LSE_GRID, 256, LSE2_SMEM>>>();
    finalize_kernel<<<1, 256>>>(out, out_size);
}

// round 11
// speedup vs baseline: 3.7350x; 1.6090x over previous
#include <cuda_runtime.h>
#include <cuda_bf16.h>
#include <cuda_fp16.h>
#include <cstdint>
#include <math.h>

#define DD 64
#define LL 64
#define DIMF 512
#define GG 256
#define MNODES 192
#define KNN 12
#define NROWS 4096
#define TAUF 0.07f
#define KH 256            // fp16 single-term GEMM K
#define LSE_GRID 296      // 2 blocks/SM persistent
#define LSE_ITEMS 1536    // 6 mats x 32 itiles x 8 j-eighths

// ---------------- device scratch (no allocations allowed) ----------------
__device__ float g_X[DD*MNODES*GG];              // fc output      [d,m,G]
__device__ float g_Y[DD*MNODES*GG];              // node features  [d,m,G]
__device__ unsigned long long g_H[DD*MNODES*3];  // incidence bitmask rows
__device__ float g_xn[3*NROWS*GG];               // normalized tn/an/vn (fp32, for diag)
__device__ __half g_xcat[3ull*NROWS*KH];         // fp16 normalized rows
__device__ float g_lsep[6*8*NROWS];              // partial row sums (mat x jq)
__device__ float g_diag[3*NROWS];                // per-row diag sim (3 pairs)
__device__ unsigned int g_item_ctr;              // lse work-steal counter

// =====================  baseline-PTX helpers =====================
#define CP_ASYNC16(dst, src) \
    asm volatile("cp.async.cg.shared.global [%0], [%1], 16;" :: "r"(dst), "l"(src) : "memory")
#define CP_COMMIT() asm volatile("cp.async.commit_group;" ::: "memory")
#define CP_WAIT1() asm volatile("cp.async.wait_group 1;" ::: "memory")
#define CP_WAIT0() asm volatile("cp.async.wait_group 0;" ::: "memory")

__device__ __forceinline__ uint32_t smem_to_u32(const void* smem_ptr) {
    uint32_t addr;
    asm("{ .reg .u64 tmp; cvta.to.shared.u64 tmp, %1; cvt.u32.u64 %0, tmp; }"
        : "=r"(addr) : "l"(smem_ptr));
    return addr;
}
__device__ __forceinline__ void ldsm_x4(uint32_t (&r)[4], uint32_t addr) {
    asm volatile("ldmatrix.sync.aligned.m8n8.x4.shared.b16 {%0,%1,%2,%3}, [%4];"
        : "=r"(r[0]), "=r"(r[1]), "=r"(r[2]), "=r"(r[3]) : "r"(addr));
}
__device__ __forceinline__ void mma16816(float (&d)[4], const uint32_t (&a)[4],
                                         uint32_t b0, uint32_t b1) {
    asm volatile("mma.sync.aligned.m16n8k16.row.col.f32.f16.f16.f32 "
        "{%0,%1,%2,%3}, {%4,%5,%6,%7}, {%8,%9}, {%0,%1,%2,%3};"
        : "+f"(d[0]), "+f"(d[1]), "+f"(d[2]), "+f"(d[3])
        : "r"(a[0]), "r"(a[1]), "r"(a[2]), "r"(a[3]), "r"(b0), "r"(b1));
}

// ===========================================================================

__device__ __forceinline__ const float* feat_row(const float* t, const float* a,
                                                 const float* v, int d, int n) {
    int mod = n >> 6;            // 0:t 1:a 2:v
    int i   = n & 63;
    const float* b = (mod == 0) ? t : (mod == 1) ? a : v;
    return b + (size_t)(d * LL + i) * DIMF;
}

__device__ __forceinline__ float wredsum(float x) {
#pragma unroll
    for (int o = 16; o; o >>= 1) x += __shfl_down_sync(0xffffffffu, x, o);
    return x;
}

// ---------------- X = feat @ W_fc + b_fc  (M=12288,K=512,N=256) ----------------
__global__ void fc_gemm_kernel(const float* __restrict__ t, const float* __restrict__ a,
                               const float* __restrict__ v, const float* __restrict__ Wfc,
                               const float* __restrict__ bfc) {
    __shared__ __align__(16) float As[16][64];
    __shared__ __align__(16) float Bs[16][64];
    int tid = threadIdx.x;
    int bm = blockIdx.y * 64, bn = blockIdx.x * 64;
    int ty = tid >> 4, tx = tid & 15;
    float acc[4][4];
#pragma unroll
    for (int i = 0; i < 4; i++)
#pragma unroll
        for (int j = 0; j < 4; j++) acc[i][j] = 0.f;

    int rA = tid >> 2;
    int kk = (tid & 3) * 4;
    int gr = bm + rA;
    const float* arow = feat_row(t, a, v, gr / MNODES, gr % MNODES);
    int rB = tid >> 4;
    int cB = (tid & 15) * 4;

    for (int k0 = 0; k0 < DIMF; k0 += 16) {
        float4 av = *(const float4*)(arow + k0 + kk);
        As[kk + 0][rA] = av.x; As[kk + 1][rA] = av.y;
        As[kk + 2][rA] = av.z; As[kk + 3][rA] = av.w;
        float4 bv = *(const float4*)(Wfc + (size_t)(k0 + rB) * GG + bn + cB);
        *(float4*)&Bs[rB][cB] = bv;
        __syncthreads();
#pragma unroll
        for (int k = 0; k < 16; k++) {
            float4 a4 = *(const float4*)&As[k][ty * 4];
            float4 b4 = *(const float4*)&Bs[k][tx * 4];
            acc[0][0] += a4.x * b4.x; acc[0][1] += a4.x * b4.y; acc[0][2] += a4.x * b4.z; acc[0][3] += a4.x * b4.w;
            acc[1][0] += a4.y * b4.x; acc[1][1] += a4.y * b4.y; acc[1][2] += a4.y * b4.z; acc[1][3] += a4.y * b4.w;
            acc[2][0] += a4.z * b4.x; acc[2][1] += a4.z * b4.y; acc[2][2] += a4.z * b4.z; acc[2][3] += a4.z * b4.w;
            acc[3][0] += a4.w * b4.x; acc[3][1] += a4.w * b4.y; acc[3][2] += a4.w * b4.z; acc[3][3] += a4.w * b4.w;
        }
        __syncthreads();
    }
#pragma unroll
    for (int i = 0; i < 4; i++) {
        int row = bm + ty * 4 + i;
#pragma unroll
        for (int j = 0; j < 4; j++) {
            int col = bn + tx * 4 + j;
            g_X[(size_t)row * GG + col] = acc[i][j] + bfc[col];
        }
    }
}

// ------ distances + top-12 + incidence; 1 block per (d, 16-row group) ------
__global__ void dist_topk_kernel(const float* __restrict__ t, const float* __restrict__ a,
                                 const float* __restrict__ v) {
    __shared__ float fr[16][DIMF];     // 32 KB
    __shared__ float sqr[16];
    __shared__ float d2s[16][MNODES];  // 12 KB
    int tid = threadIdx.x;
    int w = tid >> 5, lane = tid & 31;
    int d = blockIdx.x / 12, rg = blockIdx.x % 12;
    int r0 = rg * 16;

    for (int idx = tid; idx < 16 * DIMF; idx += 256) {
        int rr = idx >> 9, f = idx & (DIMF - 1);
        fr[rr][f] = feat_row(t, a, v, d, r0 + rr)[f];
    }
    __syncthreads();

#pragma unroll
    for (int rr = 2 * w; rr < 2 * w + 2; rr++) {
        float s = 0.f;
        for (int f = lane; f < DIMF; f += 32) { float x = fr[rr][f]; s += x * x; }
        s = wredsum(s);
        if (lane == 0) sqr[rr] = s;
    }
    __syncthreads();

    for (int it = 0; it < 12; ++it) {
        int j0 = it * 16 + w * 2;
        const float* f0 = feat_row(t, a, v, d, j0);
        const float* f1 = feat_row(t, a, v, d, j0 + 1);
        float dot0[16], dot1[16];
#pragma unroll
        for (int r = 0; r < 16; r++) { dot0[r] = 0.f; dot1[r] = 0.f; }
        float s20 = 0.f, s21 = 0.f;
        for (int f = lane; f < DIMF; f += 32) {
            float x0 = f0[f], x1 = f1[f];
            s20 += x0 * x0; s21 += x1 * x1;
#pragma unroll
            for (int r = 0; r < 16; r++) {
                float s = fr[r][f];
                dot0[r] += s * x0;
                dot1[r] += s * x1;
            }
        }
        s20 = wredsum(s20); s21 = wredsum(s21);
#pragma unroll
        for (int r = 0; r < 16; r++) {
            float dA = wredsum(dot0[r]);
            float dB = wredsum(dot1[r]);
            if (lane == 0) {
                float e0 = sqr[r] + s20 - 2.f * dA;
                float e1 = sqr[r] + s21 - 2.f * dB;
                d2s[r][j0]     = e0 > 0.f ? e0 : 0.f;
                d2s[r][j0 + 1] = e1 > 0.f ? e1 : 0.f;
            }
        }
    }
    __syncthreads();

    for (int rr = 2 * w; rr < 2 * w + 2; rr++) {
        float vv[6];
#pragma unroll
        for (int q = 0; q < 6; q++) vv[q] = d2s[rr][lane + 32 * q];
        unsigned long long m0 = 0ull, m1 = 0ull, m2 = 0ull;
        for (int itk = 0; itk < KNN; ++itk) {
            float bv = vv[0]; int bi = lane;
#pragma unroll
            for (int q = 1; q < 6; q++) {
                if (vv[q] < bv) { bv = vv[q]; bi = lane + 32 * q; }
            }
#pragma unroll
            for (int o = 16; o; o >>= 1) {
                float ov = __shfl_down_sync(0xffffffffu, bv, o);
                int   oi = __shfl_down_sync(0xffffffffu, bi, o);
                if (ov < bv || (ov == bv && oi < bi)) { bv = ov; bi = oi; }
            }
            int n = __shfl_sync(0xffffffffu, bi, 0);
            if ((n & 31) == lane) vv[n >> 5] = 3.4e38f;
            if (n < 64) m0 |= 1ull << n;
            else if (n < 128) m1 |= 1ull << (n - 64);
            else m2 |= 1ull << (n - 128);
        }
        if (lane == 0) {
            int r = r0 + rr;
            int u = r / 3;
            m0 |= 1ull << u; m1 |= 1ull << u; m2 |= 1ull << u;
            size_t base = (size_t)(d * MNODES + r) * 3;
            g_H[base] = m0; g_H[base + 1] = m1; g_H[base + 2] = m2;
        }
    }
}

// ===== fused hypergraph conv: E = H@X/deg_e, Y = H^T@E/deg_v, all in smem =====
#define HC_XS    0
#define HC_ES    49152
#define HC_HS    98304
#define HC_HT    102912
#define HC_SMEM  107520

__global__ void __launch_bounds__(256) hyperconv_kernel() {
    extern __shared__ char hsm[];
    float* Xs = (float*)(hsm + HC_XS);                       // [192][64]
    float* Es = (float*)(hsm + HC_ES);                       // [192][64]
    unsigned long long* Hs = (unsigned long long*)(hsm + HC_HS);  // [192][3]
    uint32_t* Ht = (uint32_t*)(hsm + HC_HT);                 // [192][6]
    int tid = threadIdx.x, lane = tid & 31, w = tid >> 5;
    int d = blockIdx.x, gs = blockIdx.y * 64;

    for (int idx = tid; idx < MNODES * 64; idx += 256) {
        int r = idx >> 6, c = idx & 63;
        Xs[idx] = g_X[(size_t)(d * MNODES + r) * GG + gs + c];
    }
    for (int idx = tid; idx < MNODES * 3; idx += 256)
        Hs[idx] = g_H[(size_t)d * (MNODES * 3) + idx];
    __syncthreads();

    if (w < 6) {
        int e = w * 32 + lane;
        unsigned long long r0 = Hs[e * 3 + 0], r1 = Hs[e * 3 + 1], r2 = Hs[e * 3 + 2];
        for (int n = 0; n < 64; n++) {
            uint32_t b0 = __ballot_sync(0xffffffffu, (r0 >> n) & 1ull);
            uint32_t b1 = __ballot_sync(0xffffffffu, (r1 >> n) & 1ull);
            uint32_t b2 = __ballot_sync(0xffffffffu, (r2 >> n) & 1ull);
            if (lane == 0) {
                Ht[n * 6 + w]         = b0;
                Ht[(n + 64) * 6 + w]  = b1;
                Ht[(n + 128) * 6 + w] = b2;
            }
        }
    }
    __syncthreads();

    for (int e = w; e < MNODES; e += 8) {
        float a0 = 0.f, a1 = 0.f;
        int c = 0;
#pragma unroll
        for (int wi = 0; wi < 3; wi++) {
            unsigned long long m = Hs[e * 3 + wi];
            c += __popcll(m);
            while (m) {
                int b = __ffsll((long long)m) - 1; m &= m - 1;
                int n = wi * 64 + b;
                a0 += Xs[n * 64 + lane];
                a1 += Xs[n * 64 + lane + 32];
            }
        }
        float fc2 = (float)c;
        Es[e * 64 + lane]      = a0 / fc2;
        Es[e * 64 + lane + 32] = a1 / fc2;
    }
    __syncthreads();

    for (int n = w; n < MNODES; n += 8) {
        float a0 = 0.f, a1 = 0.f;
        int c = 0;
#pragma unroll
        for (int wi = 0; wi < 6; wi++) {
            uint32_t m = Ht[n * 6 + wi];
            c += __popc(m);
            while (m) {
                int b = __ffs((int)m) - 1; m &= m - 1;
                int e = wi * 32 + b;
                a0 += Es[e * 64 + lane];
                a1 += Es[e * 64 + lane + 32];
            }
        }
        float fc2 = (float)c;
        size_t o = (size_t)(d * MNODES + n) * GG + gs;
        g_Y[o + lane]      = a0 / fc2;
        g_Y[o + lane + 32] = a1 / fc2;
    }
}

// ------------- out = relu(Y @ W_h + b_h), scattered to [4096,768] layout -------------
__global__ void wh_gemm_kernel(const float* __restrict__ Wh, const float* __restrict__ bh,
                               float* __restrict__ out) {
    __shared__ __align__(16) float As[16][64];
    __shared__ __align__(16) float Bs[16][64];
    int tid = threadIdx.x;
    int bm = blockIdx.y * 64, bn = blockIdx.x * 64;
    int ty = tid >> 4, tx = tid & 15;
    float acc[4][4];
#pragma unroll
    for (int i = 0; i < 4; i++)
#pragma unroll
        for (int j = 0; j < 4; j++) acc[i][j] = 0.f;

    int rA = tid >> 2;
    int kk = (tid & 3) * 4;
    const float* arow = g_Y + (size_t)(bm + rA) * GG;
    int rB = tid >> 4;
    int cB = (tid & 15) * 4;

    for (int k0 = 0; k0 < GG; k0 += 16) {
        float4 av = *(const float4*)(arow + k0 + kk);
        As[kk + 0][rA] = av.x; As[kk + 1][rA] = av.y;
        As[kk + 2][rA] = av.z; As[kk + 3][rA] = av.w;
        float4 bv = *(const float4*)(Wh + (size_t)(k0 + rB) * GG + bn + cB);
        *(float4*)&Bs[rB][cB] = bv;
        __syncthreads();
#pragma unroll
        for (int k = 0; k < 16; k++) {
            float4 a4 = *(const float4*)&As[k][ty * 4];
            float4 b4 = *(const float4*)&Bs[k][tx * 4];
            acc[0][0] += a4.x * b4.x; acc[0][1] += a4.x * b4.y; acc[0][2] += a4.x * b4.z; acc[0][3] += a4.x * b4.w;
            acc[1][0] += a4.y * b4.x; acc[1][1] += a4.y * b4.y; acc[1][2] += a4.y * b4.z; acc[1][3] += a4.y * b4.w;
            acc[2][0] += a4.z * b4.x; acc[2][1] += a4.z * b4.y; acc[2][2] += a4.z * b4.z; acc[2][3] += a4.z * b4.w;
            acc[3][0] += a4.w * b4.x; acc[3][1] += a4.w * b4.y; acc[3][2] += a4.w * b4.z; acc[3][3] += a4.w * b4.w;
        }
        __syncthreads();
    }
#pragma unroll
    for (int i = 0; i < 4; i++) {
        int row = bm + ty * 4 + i;
        int d = row / MNODES, n = row % MNODES;
        int mod = n >> 6, ii = n & 63;
        size_t obase = (size_t)(d * LL + ii) * 768 + (size_t)mod * GG;
#pragma unroll
        for (int j = 0; j < 4; j++) {
            int col = bn + tx * 4 + j;
            float vv = acc[i][j] + bh[col];
            out[obase + col] = vv > 0.f ? vv : 0.f;
        }
    }
}

// --------- row-normalize + fp16 rows for the GEMM-LSE ---------
__global__ void normalize_kernel(const float* __restrict__ out) {
    __shared__ float red[256];
    int tid = threadIdx.x;
    int mod = blockIdx.x / NROWS, i = blockIdx.x % NROWS;
    float x = out[(size_t)i * 768 + (size_t)mod * GG + tid];
    red[tid] = x * x; __syncthreads();
    for (int s = 128; s; s >>= 1) { if (tid < s) red[tid] += red[tid + s]; __syncthreads(); }
    float nrm = sqrtf(red[0]) + 1e-8f;
    float xn = x / nrm;
    g_xn[((size_t)mod * NROWS + i) * GG + tid] = xn;
    g_xcat[((size_t)mod * NROWS + i) * KH + tid] = __float2half(xn);
}

// ---------------- diagonal similarities + lse counter reset ----------------
__global__ void diag_kernel() {
    __shared__ float red[256];
    int tid = threadIdx.x;
    int p = blockIdx.y;
    int i = blockIdx.x;
    if (p == 0 && i == 0 && tid == 0) g_item_ctr = LSE_GRID;   // reset work-steal counter
    int ma = (p == 2) ? 1 : 0;
    int mb = (p == 0) ? 1 : 2;
    float xa = g_xn[((size_t)ma * NROWS + i) * GG + tid];
    float xb = g_xn[((size_t)mb * NROWS + i) * GG + tid];
    red[tid] = xa * xb; __syncthreads();
    for (int s = 128; s; s >>= 1) { if (tid < s) red[tid] += red[tid + s]; __syncthreads(); }
    if (tid == 0) g_diag[(size_t)p * NROWS + i] = red[0] / TAUF;
}

// ========= persistent fp16 mma.sync GEMM-LSE (K=256) with work stealing =========
// smem: A 128x256 fp16 (4 chunks of [128][64h], swizzled) = 65536
//       B double buffer 2 x 16384                          = 32768
#define LSE2_ABYTES 65536
#define LSE2_BOFF   LSE2_ABYTES
#define LSE2_BCH    16384
#define LSE2_SMEM   (LSE2_ABYTES + 2 * LSE2_BCH)   // 98304

__global__ void __launch_bounds__(256, 2) lse_mma_kernel() {
    extern __shared__ char smem[];
    __shared__ int s_item;
    uint32_t sb = smem_to_u32(smem);
    int tid = threadIdx.x, lane = tid & 31, w = tid >> 5;
    const int mx[6] = {0, 1, 0, 2, 1, 2};
    const int my[6] = {1, 0, 2, 0, 2, 1};
    int wrow = (w & 3) * 32;
    int wcol = (w >> 2) * 64;
    const float kexp = 1.44269504088896340736f / TAUF;

    int item = blockIdx.x;
    int aid = -1;
    const __half* Yp = nullptr;

    auto issueB = [&](int j0, int kc, int buf) {
#pragma unroll
        for (int q = 0; q < 4; q++) {
            int cid = q * 256 + tid;        // 0..1023
            int row = cid >> 3, c = cid & 7;
            const __half* src = Yp + (size_t)(j0 + row) * KH + kc * 64 + c * 8;
            uint32_t dst = sb + LSE2_BOFF + buf * LSE2_BCH
                         + row * 128 + ((c ^ (row & 7)) << 4);
            CP_ASYNC16(dst, src);
        }
        CP_COMMIT();
    };

    while (item < LSE_ITEMS) {
        int mat = item >> 8;             // /256
        int rem = item & 255;
        int itile = rem >> 3, jq = rem & 7;
        int i0 = itile * 128;
        Yp = g_xcat + (size_t)my[mat] * NROWS * KH;

        int na = item >> 3;
        if (na != aid) {                 // (re)load resident A tile (64 KB)
            const __half* Xp = g_xcat + (size_t)mx[mat] * NROWS * KH;
#pragma unroll 4
            for (int q = 0; q < 16; q++) {
                int cid = q * 256 + tid;     // 0..4095 16B-chunks
                int kc = cid >> 10;
                int r2 = cid & 1023;
                int row = r2 >> 3, c = r2 & 7;
                uint4 vd = *(const uint4*)(Xp + (size_t)(i0 + row) * KH + kc * 64 + c * 8);
                *(uint4*)(smem + kc * 16384 + row * 128 + ((c ^ (row & 7)) << 4)) = vd;
            }
            __syncthreads();
            aid = na;
        }

        float rs[4] = {0.f, 0.f, 0.f, 0.f};
        issueB((jq * 4) * 128, 0, 0);

        for (int jt = 0; jt < 4; jt++) {
            int j0 = (jq * 4 + jt) * 128;
            float acc[2][8][4];
#pragma unroll
            for (int mt = 0; mt < 2; mt++)
#pragma unroll
                for (int nt = 0; nt < 8; nt++)
#pragma unroll
                    for (int e = 0; e < 4; e++) acc[mt][nt][e] = 0.f;

            for (int kc = 0; kc < 4; kc++) {
                int gi = jt * 4 + kc;
                bool more = (kc < 3) || (jt < 3);
                if (more) {
                    int nkc = (kc < 3) ? kc + 1 : 0;
                    int nj0 = (kc < 3) ? j0 : j0 + 128;
                    issueB(nj0, nkc, (gi + 1) & 1);
                    CP_WAIT1();
                } else {
                    CP_WAIT0();
                }
                __syncthreads();

                uint32_t abase = sb + kc * 16384;
                uint32_t bbase = sb + LSE2_BOFF + (gi & 1) * LSE2_BCH;
#pragma unroll
                for (int kq = 0; kq < 4; kq++) {
                    uint32_t afr[2][4];
#pragma unroll
                    for (int mt = 0; mt < 2; mt++) {
                        int row = wrow + mt * 16 + (lane & 7) + ((lane >> 3) & 1) * 8;
                        int c = kq * 2 + (lane >> 4);
                        ldsm_x4(afr[mt], abase + row * 128 + ((c ^ (row & 7)) << 4));
                    }
#pragma unroll
                    for (int nt = 0; nt < 8; nt += 2) {
                        int quad = lane >> 3;
                        int brow = wcol + (nt + (quad >> 1)) * 8 + (lane & 7);
                        int bc = kq * 2 + (quad & 1);
                        uint32_t bf[4];
                        ldsm_x4(bf, bbase + brow * 128 + ((bc ^ (brow & 7)) << 4));
                        mma16816(acc[0][nt],     afr[0], bf[0], bf[1]);
                        mma16816(acc[1][nt],     afr[1], bf[0], bf[1]);
                        mma16816(acc[0][nt + 1], afr[0], bf[2], bf[3]);
                        mma16816(acc[1][nt + 1], afr[1], bf[2], bf[3]);
                    }
                }
                __syncthreads();
            }

#pragma unroll
            for (int mt = 0; mt < 2; mt++)
#pragma unroll
                for (int nt = 0; nt < 8; nt++) {
                    rs[2 * mt + 0] += exp2f(acc[mt][nt][0] * kexp) + exp2f(acc[mt][nt][1] * kexp);
                    rs[2 * mt + 1] += exp2f(acc[mt][nt][2] * kexp) + exp2f(acc[mt][nt][3] * kexp);
                }
        }

        // reduce across 4 lanes sharing a row (distinct cols)
#pragma unroll
        for (int e = 0; e < 4; e++) {
            rs[e] += __shfl_xor_sync(0xffffffffu, rs[e], 1);
            rs[e] += __shfl_xor_sync(0xffffffffu, rs[e], 2);
        }

        // deterministic 2-slot reduction (no float atomics)
        float* rs2 = (float*)(smem + LSE2_BOFF);   // B buffers idle here
        if ((lane & 3) == 0) {
            int g = lane >> 2;
            int grp = (w >> 2) * 128;
            rs2[grp + wrow + g]          = rs[0];
            rs2[grp + wrow + g + 8]      = rs[1];
            rs2[grp + wrow + 16 + g]     = rs[2];
            rs2[grp + wrow + 24 + g]     = rs[3];
        }
        __syncthreads();
        if (tid < 128)
            g_lsep[((size_t)mat * 8 + jq) * NROWS + i0 + tid] = rs2[tid] + rs2[128 + tid];
        __syncthreads();   // rs2 lives in B buffer space; protect vs next item's issueB

        if (tid == 0) s_item = (int)atomicAdd(&g_item_ctr, 1u);
        __syncthreads();
        item = s_item;
    }
}

// ---------------- deterministic final reduction -> loss ----------------
__global__ void finalize_kernel(float* __restrict__ out, int out_size) {
    __shared__ double red[256];
    int tid = threadIdx.x;
    double sl = 0.0;
    for (int i = tid; i < 6 * NROWS; i += 256) {
        int m = i >> 12, r = i & (NROWS - 1);
        float s = 0.f;
#pragma unroll
        for (int jq = 0; jq < 8; jq++)
            s += g_lsep[((size_t)m * 8 + jq) * NROWS + r];
        sl += (double)logf(s);
    }
    red[tid] = sl; __syncthreads();
    for (int s = 128; s; s >>= 1) { if (tid < s) red[tid] += red[tid + s]; __syncthreads(); }
    double SL = red[0]; __syncthreads();
    double sd = 0.0;
    for (int i = tid; i < 3 * NROWS; i += 256) sd += (double)g_diag[i];
    red[tid] = sd; __syncthreads();
    for (int s = 128; s; s >>= 1) { if (tid < s) red[tid] += red[tid + s]; __syncthreads(); }
    double SD = red[0];
    if (tid == 0 && out_size > NROWS * 768) {
        double loss = SL / (6.0 * NROWS) - SD / (3.0 * NROWS);
        out[NROWS * 768] = (float)loss;
    }
}

// ---------------- launch ----------------
extern "C" void kernel_launch(void* const* d_in, const int* in_sizes, int n_in,
                              void* d_out, int out_size) {
    const float* t   = (const float*)d_in[0];
    const float* a   = (const float*)d_in[1];
    const float* v   = (const float*)d_in[2];
    const float* Wfc = (const float*)d_in[3];
    const float* bfc = (const float*)d_in[4];
    const float* Wh  = (const float*)d_in[5];
    const float* bh  = (const float*)d_in[6];
    float* out = (float*)d_out;

    cudaFuncSetAttribute(lse_mma_kernel,
                         cudaFuncAttributeMaxDynamicSharedMemorySize, LSE2_SMEM);
    cudaFuncSetAttribute(hyperconv_kernel,
                         cudaFuncAttributeMaxDynamicSharedMemorySize, HC_SMEM);

    fc_gemm_kernel<<<dim3(GG / 64, (DD * MNODES) / 64), 256>>>(t, a, v, Wfc, bfc);
    dist_topk_kernel<<<DD * 12, 256>>>(t, a, v);
    hyperconv_kernel<<<dim3(DD, 4), 256, HC_SMEM>>>();
    wh_gemm_kernel<<<dim3(GG / 64, (DD * MNODES) / 64), 256>>>(Wh, bh, out);
    normalize_kernel<<<3 * NROWS, 256>>>(out);
    diag_kernel<<<dim3(NROWS, 3), 256>>>();
    lse_mma_kernel<<<LSE_GRID, 256, LSE2_SMEM>>>();
    finalize_kernel<<<1, 256>>>(out, out_size);
}

// round 14
// speedup vs baseline: 4.3995x; 1.1779x over previous
#include <cuda_runtime.h>
#include <cuda_bf16.h>
#include <cuda_fp16.h>
#include <cstdint>
#include <math.h>

#define DD 64
#define LL 64
#define DIMF 512
#define GG 256
#define MNODES 192
#define KNN 12
#define NROWS 4096
#define TAUF 0.07f
#define KH 256            // fp16 single-term GEMM K (contrastive)
#define LSE_GRID 296      // 2 blocks/SM persistent
#define LSE_ITEMS 1536    // 6 mats x 32 itiles x 8 j-eighths

// ---------------- device scratch (no allocations allowed) ----------------
__device__ float g_X[DD*MNODES*GG];              // fc output      [d,m,G]
__device__ unsigned long long g_H[DD*MNODES*3];  // incidence bitmask rows
__device__ float g_xn[3*NROWS*GG];               // normalized tn/an/vn (fp32, for diag)
__device__ __half g_xcat[3ull*NROWS*KH];         // fp16 normalized rows
__device__ float g_lsep[6*8*NROWS];              // partial row sums (mat x jq)
__device__ float g_diag[3*NROWS];                // per-row diag sim (3 pairs)
__device__ unsigned int g_item_ctr;              // lse work-steal counter
__device__ __half g_fcA[(size_t)DD*MNODES*1024]; // feat hi/lo  [12288][Ah(512)|Al(512)]
__device__ __half g_fcB[256*1024];               // WfcT hi/lo  [256][Wh(512)|Wl(512)]
__device__ __half g_whA[(size_t)DD*MNODES*512];  // Y hi/lo     [12288][Yh(256)|Yl(256)]
__device__ __half g_whB[256*512];                // WhT hi/lo   [256][Wh(256)|Wl(256)]

// =====================  baseline-PTX helpers =====================
#define CP_ASYNC16(dst, src) \
    asm volatile("cp.async.cg.shared.global [%0], [%1], 16;" :: "r"(dst), "l"(src) : "memory")
#define CP_COMMIT() asm volatile("cp.async.commit_group;" ::: "memory")
#define CP_WAIT1() asm volatile("cp.async.wait_group 1;" ::: "memory")
#define CP_WAIT0() asm volatile("cp.async.wait_group 0;" ::: "memory")

__device__ __forceinline__ uint32_t smem_to_u32(const void* smem_ptr) {
    uint32_t addr;
    asm("{ .reg .u64 tmp; cvta.to.shared.u64 tmp, %1; cvt.u32.u64 %0, tmp; }"
        : "=r"(addr) : "l"(smem_ptr));
    return addr;
}
__device__ __forceinline__ void ldsm_x4(uint32_t (&r)[4], uint32_t addr) {
    asm volatile("ldmatrix.sync.aligned.m8n8.x4.shared.b16 {%0,%1,%2,%3}, [%4];"
        : "=r"(r[0]), "=r"(r[1]), "=r"(r[2]), "=r"(r[3]) : "r"(addr));
}
__device__ __forceinline__ void mma16816(float (&d)[4], const uint32_t (&a)[4],
                                         uint32_t b0, uint32_t b1) {
    asm volatile("mma.sync.aligned.m16n8k16.row.col.f32.f16.f16.f32 "
        "{%0,%1,%2,%3}, {%4,%5,%6,%7}, {%8,%9}, {%0,%1,%2,%3};"
        : "+f"(d[0]), "+f"(d[1]), "+f"(d[2]), "+f"(d[3])
        : "r"(a[0]), "r"(a[1]), "r"(a[2]), "r"(a[3]), "r"(b0), "r"(b1));
}

// ===========================================================================

__device__ __forceinline__ const float* feat_row(const float* t, const float* a,
                                                 const float* v, int d, int n) {
    int mod = n >> 6;            // 0:t 1:a 2:v
    int i   = n & 63;
    const float* b = (mod == 0) ? t : (mod == 1) ? a : v;
    return b + (size_t)(d * LL + i) * DIMF;
}

__device__ __forceinline__ float wredsum(float x) {
#pragma unroll
    for (int o = 16; o; o >>= 1) x += __shfl_down_sync(0xffffffffu, x, o);
    return x;
}

// ---------------- prep: features -> [Ah|Al] fp16 rows ----------------
__global__ void fc_prep_a_kernel(const float* __restrict__ t, const float* __restrict__ a,
                                 const float* __restrict__ v) {
    int row = blockIdx.x, tid = threadIdx.x;
    const float* src = feat_row(t, a, v, row / MNODES, row % MNODES);
    size_t base = (size_t)row * 1024;
#pragma unroll
    for (int q = 0; q < 2; q++) {
        int f = q * 256 + tid;
        float x = src[f];
        __half xh = __float2half(x);
        __half xl = __float2half(x - __half2float(xh));
        g_fcA[base + f] = xh;
        g_fcA[base + 512 + f] = xl;
    }
}

// ---------------- prep: W_fc^T -> [Wh|Wl] fp16 rows ----------------
__global__ void fc_prep_b_kernel(const float* __restrict__ Wfc) {
    int n = blockIdx.x, tid = threadIdx.x;
    size_t base = (size_t)n * 1024;
#pragma unroll
    for (int q = 0; q < 2; q++) {
        int k = q * 256 + tid;
        float x = Wfc[(size_t)k * GG + n];
        __half xh = __float2half(x);
        __half xl = __float2half(x - __half2float(xh));
        g_fcB[base + k] = xh;
        g_fcB[base + 512 + k] = xl;
    }
}

// ---------------- prep: W_h^T -> [Wh|Wl] fp16 rows ----------------
__global__ void wh_prep_b_kernel(const float* __restrict__ Wh) {
    int n = blockIdx.x, k = threadIdx.x;
    float x = Wh[(size_t)k * GG + n];
    __half xh = __float2half(x);
    __half xl = __float2half(x - __half2float(xh));
    g_whB[(size_t)n * 512 + k] = xh;
    g_whB[(size_t)n * 512 + 256 + k] = xl;
}

// ===== split-fp16 MMA GEMM: C(12288x256) = A(.,K) * B(256,K)^T, 3-term hi/lo =====
// WHICH=0: A=g_fcA (K=1024 halves), B=g_fcB, epi: g_X = C + bias.
// WHICH=1: A=g_whA (K=512 halves),  B=g_whB, epi: out = relu(C + bias) scattered.
// Chunks gc in [0, 3*HA): term1 Ah*Bh, term2 Ah*Bl, term3 Al*Bh (storage remap).
#define GS_BOFF 32768
#define GS_SMEM 49152

template<int HA, int WHICH>
__global__ void __launch_bounds__(256, 2) gemm_split_kernel(
    const float* __restrict__ bias, float* __restrict__ outp)
{
    extern __shared__ char smem[];
    uint32_t sb = smem_to_u32(smem);
    const __half* Ac = (WHICH == 0) ? g_fcA : g_whA;   // device-side symbol refs
    const __half* Bc = (WHICH == 0) ? g_fcB : g_whB;
    int tid = threadIdx.x, lane = tid & 31, w = tid >> 5;
    int i0 = blockIdx.y * 128, j0 = blockIdx.x * 64;
    int wrow = (w & 3) * 32, wcol = (w >> 2) * 32;
    const int KA = HA * 128;     // halves per storage row (hi+lo)
    const int NCH = 3 * HA;

    auto issue = [&](int gc, int buf) {
        int ka = (gc >= HA) ? gc - HA : gc;            // Ah for t1/t2, Al for t3
        int kb = (gc >= 2 * HA) ? gc - 2 * HA : gc;    // Bh for t1/t3, Bl for t2
#pragma unroll
        for (int q = 0; q < 4; q++) {
            int cid = q * 256 + tid;       // 0..1023
            int row = cid >> 3, c = cid & 7;
            const __half* src = Ac + (size_t)(i0 + row) * KA + ka * 64 + c * 8;
            uint32_t dst = sb + buf * 16384 + row * 128 + ((c ^ (row & 7)) << 4);
            CP_ASYNC16(dst, src);
        }
#pragma unroll
        for (int q = 0; q < 2; q++) {
            int cid = q * 256 + tid;       // 0..511
            int row = cid >> 3, c = cid & 7;
            const __half* src = Bc + (size_t)(j0 + row) * KA + kb * 64 + c * 8;
            uint32_t dst = sb + GS_BOFF + buf * 8192 + row * 128 + ((c ^ (row & 7)) << 4);
            CP_ASYNC16(dst, src);
        }
        CP_COMMIT();
    };

    float acc[2][4][4];
#pragma unroll
    for (int mt = 0; mt < 2; mt++)
#pragma unroll
        for (int nt = 0; nt < 4; nt++)
#pragma unroll
            for (int e = 0; e < 4; e++) acc[mt][nt][e] = 0.f;

    issue(0, 0);
    for (int gc = 0; gc < NCH; gc++) {
        if (gc + 1 < NCH) { issue(gc + 1, (gc + 1) & 1); CP_WAIT1(); }
        else             { CP_WAIT0(); }
        __syncthreads();

        uint32_t abase = sb + (gc & 1) * 16384;
        uint32_t bbase = sb + GS_BOFF + (gc & 1) * 8192;
#pragma unroll
        for (int kq = 0; kq < 4; kq++) {
            uint32_t afr[2][4];
#pragma unroll
            for (int mt = 0; mt < 2; mt++) {
                int row = wrow + mt * 16 + (lane & 7) + ((lane >> 3) & 1) * 8;
                int c = kq * 2 + (lane >> 4);
                ldsm_x4(afr[mt], abase + row * 128 + ((c ^ (row & 7)) << 4));
            }
#pragma unroll
            for (int nt = 0; nt < 4; nt += 2) {
                int quad = lane >> 3;
                int brow = wcol + (nt + (quad >> 1)) * 8 + (lane & 7);
                int bc = kq * 2 + (quad & 1);
                uint32_t bf[4];
                ldsm_x4(bf, bbase + brow * 128 + ((bc ^ (brow & 7)) << 4));
                mma16816(acc[0][nt],     afr[0], bf[0], bf[1]);
                mma16816(acc[1][nt],     afr[1], bf[0], bf[1]);
                mma16816(acc[0][nt + 1], afr[0], bf[2], bf[3]);
                mma16816(acc[1][nt + 1], afr[1], bf[2], bf[3]);
            }
        }
        __syncthreads();
    }

#pragma unroll
    for (int mt = 0; mt < 2; mt++)
#pragma unroll
        for (int nt = 0; nt < 4; nt++)
#pragma unroll
            for (int e = 0; e < 4; e++) {
                int r = i0 + wrow + mt * 16 + (lane >> 2) + ((e >> 1) << 3);
                int col = j0 + wcol + nt * 8 + (lane & 3) * 2 + (e & 1);
                float val = acc[mt][nt][e] + bias[col];
                if (WHICH == 0) {
                    g_X[(size_t)r * GG + col] = val;
                } else {
                    int d = r / MNODES, n = r % MNODES;
                    int mod = n >> 6, ii = n & 63;
                    size_t obase = (size_t)(d * LL + ii) * 768 + (size_t)mod * GG;
                    outp[obase + col] = val > 0.f ? val : 0.f;
                }
            }
}

// ------ distances + top-12 + incidence; 1 block per (d, 16-row group) ------
__global__ void dist_topk_kernel(const float* __restrict__ t, const float* __restrict__ a,
                                 const float* __restrict__ v) {
    __shared__ float fr[16][DIMF];     // 32 KB
    __shared__ float sqr[16];
    __shared__ float d2s[16][MNODES];  // 12 KB
    int tid = threadIdx.x;
    int w = tid >> 5, lane = tid & 31;
    int d = blockIdx.x / 12, rg = blockIdx.x % 12;
    int r0 = rg * 16;

    for (int idx = tid; idx < 16 * DIMF; idx += 256) {
        int rr = idx >> 9, f = idx & (DIMF - 1);
        fr[rr][f] = feat_row(t, a, v, d, r0 + rr)[f];
    }
    __syncthreads();

#pragma unroll
    for (int rr = 2 * w; rr < 2 * w + 2; rr++) {
        float s = 0.f;
        for (int f = lane; f < DIMF; f += 32) { float x = fr[rr][f]; s += x * x; }
        s = wredsum(s);
        if (lane == 0) sqr[rr] = s;
    }
    __syncthreads();

    for (int it = 0; it < 12; ++it) {
        int j0 = it * 16 + w * 2;
        const float* f0 = feat_row(t, a, v, d, j0);
        const float* f1 = feat_row(t, a, v, d, j0 + 1);
        float dot0[16], dot1[16];
#pragma unroll
        for (int r = 0; r < 16; r++) { dot0[r] = 0.f; dot1[r] = 0.f; }
        float s20 = 0.f, s21 = 0.f;
        for (int f = lane; f < DIMF; f += 32) {
            float x0 = f0[f], x1 = f1[f];
            s20 += x0 * x0; s21 += x1 * x1;
#pragma unroll
            for (int r = 0; r < 16; r++) {
                float s = fr[r][f];
                dot0[r] += s * x0;
                dot1[r] += s * x1;
            }
        }
        s20 = wredsum(s20); s21 = wredsum(s21);
#pragma unroll
        for (int r = 0; r < 16; r++) {
            float dA = wredsum(dot0[r]);
            float dB = wredsum(dot1[r]);
            if (lane == 0) {
                float e0 = sqr[r] + s20 - 2.f * dA;
                float e1 = sqr[r] + s21 - 2.f * dB;
                d2s[r][j0]     = e0 > 0.f ? e0 : 0.f;
                d2s[r][j0 + 1] = e1 > 0.f ? e1 : 0.f;
            }
        }
    }
    __syncthreads();

    for (int rr = 2 * w; rr < 2 * w + 2; rr++) {
        float vv[6];
#pragma unroll
        for (int q = 0; q < 6; q++) vv[q] = d2s[rr][lane + 32 * q];
        unsigned long long m0 = 0ull, m1 = 0ull, m2 = 0ull;
        for (int itk = 0; itk < KNN; ++itk) {
            float bv = vv[0]; int bi = lane;
#pragma unroll
            for (int q = 1; q < 6; q++) {
                if (vv[q] < bv) { bv = vv[q]; bi = lane + 32 * q; }
            }
#pragma unroll
            for (int o = 16; o; o >>= 1) {
                float ov = __shfl_down_sync(0xffffffffu, bv, o);
                int   oi = __shfl_down_sync(0xffffffffu, bi, o);
                if (ov < bv || (ov == bv && oi < bi)) { bv = ov; bi = oi; }
            }
            int n = __shfl_sync(0xffffffffu, bi, 0);
            if ((n & 31) == lane) vv[n >> 5] = 3.4e38f;
            if (n < 64) m0 |= 1ull << n;
            else if (n < 128) m1 |= 1ull << (n - 64);
            else m2 |= 1ull << (n - 128);
        }
        if (lane == 0) {
            int r = r0 + rr;
            int u = r / 3;
            m0 |= 1ull << u; m1 |= 1ull << u; m2 |= 1ull << u;
            size_t base = (size_t)(d * MNODES + r) * 3;
            g_H[base] = m0; g_H[base + 1] = m1; g_H[base + 2] = m2;
        }
    }
}

// ===== fused hypergraph conv: E = H@X/deg_e, Y = H^T@E/deg_v, all in smem =====
#define HC_XS    0
#define HC_ES    49152
#define HC_HS    98304
#define HC_HT    102912
#define HC_SMEM  107520

__global__ void __launch_bounds__(256) hyperconv_kernel() {
    extern __shared__ char hsm[];
    float* Xs = (float*)(hsm + HC_XS);                       // [192][64]
    float* Es = (float*)(hsm + HC_ES);                       // [192][64]
    unsigned long long* Hs = (unsigned long long*)(hsm + HC_HS);  // [192][3]
    uint32_t* Ht = (uint32_t*)(hsm + HC_HT);                 // [192][6]
    int tid = threadIdx.x, lane = tid & 31, w = tid >> 5;
    int d = blockIdx.x, gs = blockIdx.y * 64;

    for (int idx = tid; idx < MNODES * 64; idx += 256) {
        int r = idx >> 6, c = idx & 63;
        Xs[idx] = g_X[(size_t)(d * MNODES + r) * GG + gs + c];
    }
    for (int idx = tid; idx < MNODES * 3; idx += 256)
        Hs[idx] = g_H[(size_t)d * (MNODES * 3) + idx];
    __syncthreads();

    if (w < 6) {
        int e = w * 32 + lane;
        unsigned long long r0 = Hs[e * 3 + 0], r1 = Hs[e * 3 + 1], r2 = Hs[e * 3 + 2];
        for (int n = 0; n < 64; n++) {
            uint32_t b0 = __ballot_sync(0xffffffffu, (r0 >> n) & 1ull);
            uint32_t b1 = __ballot_sync(0xffffffffu, (r1 >> n) & 1ull);
            uint32_t b2 = __ballot_sync(0xffffffffu, (r2 >> n) & 1ull);
            if (lane == 0) {
                Ht[n * 6 + w]         = b0;
                Ht[(n + 64) * 6 + w]  = b1;
                Ht[(n + 128) * 6 + w] = b2;
            }
        }
    }
    __syncthreads();

    for (int e = w; e < MNODES; e += 8) {
        float a0 = 0.f, a1 = 0.f;
        int c = 0;
#pragma unroll
        for (int wi = 0; wi < 3; wi++) {
            unsigned long long m = Hs[e * 3 + wi];
            c += __popcll(m);
            while (m) {
                int b = __ffsll((long long)m) - 1; m &= m - 1;
                int n = wi * 64 + b;
                a0 += Xs[n * 64 + lane];
                a1 += Xs[n * 64 + lane + 32];
            }
        }
        float fc2 = (float)c;
        Es[e * 64 + lane]      = a0 / fc2;
        Es[e * 64 + lane + 32] = a1 / fc2;
    }
    __syncthreads();

    for (int n = w; n < MNODES; n += 8) {
        float a0 = 0.f, a1 = 0.f;
        int c = 0;
#pragma unroll
        for (int wi = 0; wi < 6; wi++) {
            uint32_t m = Ht[n * 6 + wi];
            c += __popc(m);
            while (m) {
                int b = __ffs((int)m) - 1; m &= m - 1;
                int e = wi * 32 + b;
                a0 += Es[e * 64 + lane];
                a1 += Es[e * 64 + lane + 32];
            }
        }
        float fc2 = (float)c;
        float y0 = a0 / fc2, y1 = a1 / fc2;
        size_t base = (size_t)(d * MNODES + n) * 512;
        __half y0h = __float2half(y0);
        __half y1h = __float2half(y1);
        g_whA[base + gs + lane]            = y0h;
        g_whA[base + gs + lane + 32]       = y1h;
        g_whA[base + 256 + gs + lane]      = __float2half(y0 - __half2float(y0h));
        g_whA[base + 256 + gs + lane + 32] = __float2half(y1 - __half2float(y1h));
    }
}

// --------- row-normalize + fp16 rows for the GEMM-LSE ---------
__global__ void normalize_kernel(const float* __restrict__ out) {
    __shared__ float red[256];
    int tid = threadIdx.x;
    int mod = blockIdx.x / NROWS, i = blockIdx.x % NROWS;
    float x = out[(size_t)i * 768 + (size_t)mod * GG + tid];
    red[tid] = x * x; __syncthreads();
    for (int s = 128; s; s >>= 1) { if (tid < s) red[tid] += red[tid + s]; __syncthreads(); }
    float nrm = sqrtf(red[0]) + 1e-8f;
    float xn = x / nrm;
    g_xn[((size_t)mod * NROWS + i) * GG + tid] = xn;
    g_xcat[((size_t)mod * NROWS + i) * KH + tid] = __float2half(xn);
}

// ---------------- diagonal similarities + lse counter reset ----------------
__global__ void diag_kernel() {
    __shared__ float red[256];
    int tid = threadIdx.x;
    int p = blockIdx.y;
    int i = blockIdx.x;
    if (p == 0 && i == 0 && tid == 0) g_item_ctr = LSE_GRID;   // reset work-steal counter
    int ma = (p == 2) ? 1 : 0;
    int mb = (p == 0) ? 1 : 2;
    float xa = g_xn[((size_t)ma * NROWS + i) * GG + tid];
    float xb = g_xn[((size_t)mb * NROWS + i) * GG + tid];
    red[tid] = xa * xb; __syncthreads();
    for (int s = 128; s; s >>= 1) { if (tid < s) red[tid] += red[tid + s]; __syncthreads(); }
    if (tid == 0) g_diag[(size_t)p * NROWS + i] = red[0] / TAUF;
}

// ========= persistent fp16 mma.sync GEMM-LSE (K=256) with work stealing =========
#define LSE2_ABYTES 65536
#define LSE2_BOFF   LSE2_ABYTES
#define LSE2_BCH    16384
#define LSE2_SMEM   (LSE2_ABYTES + 2 * LSE2_BCH)   // 98304

__global__ void __launch_bounds__(256, 2) lse_mma_kernel() {
    extern __shared__ char smem[];
    __shared__ int s_item;
    uint32_t sb = smem_to_u32(smem);
    int tid = threadIdx.x, lane = tid & 31, w = tid >> 5;
    const int mx[6] = {0, 1, 0, 2, 1, 2};
    const int my[6] = {1, 0, 2, 0, 2, 1};
    int wrow = (w & 3) * 32;
    int wcol = (w >> 2) * 64;
    const float kexp = 1.44269504088896340736f / TAUF;

    int item = blockIdx.x;
    int aid = -1;
    const __half* Yp = nullptr;

    auto issueB = [&](int j0, int kc, int buf) {
#pragma unroll
        for (int q = 0; q < 4; q++) {
            int cid = q * 256 + tid;        // 0..1023
            int row = cid >> 3, c = cid & 7;
            const __half* src = Yp + (size_t)(j0 + row) * KH + kc * 64 + c * 8;
            uint32_t dst = sb + LSE2_BOFF + buf * LSE2_BCH
                         + row * 128 + ((c ^ (row & 7)) << 4);
            CP_ASYNC16(dst, src);
        }
        CP_COMMIT();
    };

    while (item < LSE_ITEMS) {
        int mat = item >> 8;             // /256
        int rem = item & 255;
        int itile = rem >> 3, jq = rem & 7;
        int i0 = itile * 128;
        Yp = g_xcat + (size_t)my[mat] * NROWS * KH;

        int na = item >> 3;
        if (na != aid) {                 // (re)load resident A tile (64 KB)
            const __half* Xp = g_xcat + (size_t)mx[mat] * NROWS * KH;
#pragma unroll 4
            for (int q = 0; q < 16; q++) {
                int cid = q * 256 + tid;     // 0..4095 16B-chunks
                int kc = cid >> 10;
                int r2 = cid & 1023;
                int row = r2 >> 3, c = r2 & 7;
                uint4 vd = *(const uint4*)(Xp + (size_t)(i0 + row) * KH + kc * 64 + c * 8);
                *(uint4*)(smem + kc * 16384 + row * 128 + ((c ^ (row & 7)) << 4)) = vd;
            }
            __syncthreads();
            aid = na;
        }

        float rs[4] = {0.f, 0.f, 0.f, 0.f};
        issueB((jq * 4) * 128, 0, 0);

        for (int jt = 0; jt < 4; jt++) {
            int j0 = (jq * 4 + jt) * 128;
            float acc[2][8][4];
#pragma unroll
            for (int mt = 0; mt < 2; mt++)
#pragma unroll
                for (int nt = 0; nt < 8; nt++)
#pragma unroll
                    for (int e = 0; e < 4; e++) acc[mt][nt][e] = 0.f;

            for (int kc = 0; kc < 4; kc++) {
                int gi = jt * 4 + kc;
                bool more = (kc < 3) || (jt < 3);
                if (more) {
                    int nkc = (kc < 3) ? kc + 1 : 0;
                    int nj0 = (kc < 3) ? j0 : j0 + 128;
                    issueB(nj0, nkc, (gi + 1) & 1);
                    CP_WAIT1();
                } else {
                    CP_WAIT0();
                }
                __syncthreads();

                uint32_t abase = sb + kc * 16384;
                uint32_t bbase = sb + LSE2_BOFF + (gi & 1) * LSE2_BCH;
#pragma unroll
                for (int kq = 0; kq < 4; kq++) {
                    uint32_t afr[2][4];
#pragma unroll
                    for (int mt = 0; mt < 2; mt++) {
                        int row = wrow + mt * 16 + (lane & 7) + ((lane >> 3) & 1) * 8;
                        int c = kq * 2 + (lane >> 4);
                        ldsm_x4(afr[mt], abase + row * 128 + ((c ^ (row & 7)) << 4));
                    }
#pragma unroll
                    for (int nt = 0; nt < 8; nt += 2) {
                        int quad = lane >> 3;
                        int brow = wcol + (nt + (quad >> 1)) * 8 + (lane & 7);
                        int bc = kq * 2 + (quad & 1);
                        uint32_t bf[4];
                        ldsm_x4(bf, bbase + brow * 128 + ((bc ^ (brow & 7)) << 4));
                        mma16816(acc[0][nt],     afr[0], bf[0], bf[1]);
                        mma16816(acc[1][nt],     afr[1], bf[0], bf[1]);
                        mma16816(acc[0][nt + 1], afr[0], bf[2], bf[3]);
                        mma16816(acc[1][nt + 1], afr[1], bf[2], bf[3]);
                    }
                }
                __syncthreads();
            }

#pragma unroll
            for (int mt = 0; mt < 2; mt++)
#pragma unroll
                for (int nt = 0; nt < 8; nt++) {
                    rs[2 * mt + 0] += exp2f(acc[mt][nt][0] * kexp) + exp2f(acc[mt][nt][1] * kexp);
                    rs[2 * mt + 1] += exp2f(acc[mt][nt][2] * kexp) + exp2f(acc[mt][nt][3] * kexp);
                }
        }

#pragma unroll
        for (int e = 0; e < 4; e++) {
            rs[e] += __shfl_xor_sync(0xffffffffu, rs[e], 1);
            rs[e] += __shfl_xor_sync(0xffffffffu, rs[e], 2);
        }

        float* rs2 = (float*)(smem + LSE2_BOFF);   // B buffers idle here
        if ((lane & 3) == 0) {
            int g = lane >> 2;
            int grp = (w >> 2) * 128;
            rs2[grp + wrow + g]          = rs[0];
            rs2[grp + wrow + g + 8]      = rs[1];
            rs2[grp + wrow + 16 + g]     = rs[2];
            rs2[grp + wrow + 24 + g]     = rs[3];
        }
        __syncthreads();
        if (tid < 128)
            g_lsep[((size_t)mat * 8 + jq) * NROWS + i0 + tid] = rs2[tid] + rs2[128 + tid];
        __syncthreads();

        if (tid == 0) s_item = (int)atomicAdd(&g_item_ctr, 1u);
        __syncthreads();
        item = s_item;
    }
}

// ---------------- deterministic final reduction -> loss ----------------
__global__ void finalize_kernel(float* __restrict__ out, int out_size) {
    __shared__ double red[256];
    int tid = threadIdx.x;
    double sl = 0.0;
    for (int i = tid; i < 6 * NROWS; i += 256) {
        int m = i >> 12, r = i & (NROWS - 1);
        float s = 0.f;
#pragma unroll
        for (int jq = 0; jq < 8; jq++)
            s += g_lsep[((size_t)m * 8 + jq) * NROWS + r];
        sl += (double)logf(s);
    }
    red[tid] = sl; __syncthreads();
    for (int s = 128; s; s >>= 1) { if (tid < s) red[tid] += red[tid + s]; __syncthreads(); }
    double SL = red[0]; __syncthreads();
    double sd = 0.0;
    for (int i = tid; i < 3 * NROWS; i += 256) sd += (double)g_diag[i];
    red[tid] = sd; __syncthreads();
    for (int s = 128; s; s >>= 1) { if (tid < s) red[tid] += red[tid + s]; __syncthreads(); }
    double SD = red[0];
    if (tid == 0 && out_size > NROWS * 768) {
        double loss = SL / (6.0 * NROWS) - SD / (3.0 * NROWS);
        out[NROWS * 768] = (float)loss;
    }
}

// ---------------- launch ----------------
extern "C" void kernel_launch(void* const* d_in, const int* in_sizes, int n_in,
                              void* d_out, int out_size) {
    const float* t   = (const float*)d_in[0];
    const float* a   = (const float*)d_in[1];
    const float* v   = (const float*)d_in[2];
    const float* Wfc = (const float*)d_in[3];
    const float* bfc = (const float*)d_in[4];
    const float* Wh  = (const float*)d_in[5];
    const float* bh  = (const float*)d_in[6];
    float* out = (float*)d_out;

    cudaFuncSetAttribute(lse_mma_kernel,
                         cudaFuncAttributeMaxDynamicSharedMemorySize, LSE2_SMEM);
    cudaFuncSetAttribute(hyperconv_kernel,
                         cudaFuncAttributeMaxDynamicSharedMemorySize, HC_SMEM);
    cudaFuncSetAttribute(gemm_split_kernel<8, 0>,
                         cudaFuncAttributeMaxDynamicSharedMemorySize, GS_SMEM);
    cudaFuncSetAttribute(gemm_split_kernel<4, 1>,
                         cudaFuncAttributeMaxDynamicSharedMemorySize, GS_SMEM);

    fc_prep_a_kernel<<<DD * MNODES, 256>>>(t, a, v);
    fc_prep_b_kernel<<<GG, 256>>>(Wfc);
    wh_prep_b_kernel<<<GG, 256>>>(Wh);
    gemm_split_kernel<8, 0><<<dim3(4, 96), 256, GS_SMEM>>>(bfc, nullptr);
    dist_topk_kernel<<<DD * 12, 256>>>(t, a, v);
    hyperconv_kernel<<<dim3(DD, 4), 256, HC_SMEM>>>();
    gemm_split_kernel<4, 1><<<dim3(4, 96), 256, GS_SMEM>>>(bh, out);
    normalize_kernel<<<3 * NROWS, 256>>>(out);
    diag_kernel<<<dim3(NROWS, 3), 256>>>();
    lse_mma_kernel<<<LSE_GRID, 256, LSE2_SMEM>>>();
    finalize_kernel<<<1, 256>>>(out, out_size);
}